// round 1
// baseline (speedup 1.0000x reference)
#include <cuda_runtime.h>
#include <math.h>

// Problem constants
#define NWIN 1024          // windows
#define NTOK 64            // tokens per window
#define CD   192           // channels
#define C3   576           // 3*C
#define OUT_ELEMS 12582912 // 4*128*128*192
#define ATTN_SCALE 0.17677669529663687f  // 32^-0.5

// Scratch: qkv[wb][n][576]  (q: 0..191, k: 192..383, v: 384..575), ~151MB
static __device__ __align__(16) float g_qkv[NWIN * NTOK * C3];

// ---------------------------------------------------------------------------
// Kernel 1: QKV GEMM with fused shifted-window gather.
//   M = 65536 (window tokens), K = 192, N = 576.
//   Block tile 128x64, K-chunk 16, 256 threads, 8x4 micro-tile.
//   Each 128-row tile covers exactly 2 windows.
// ---------------------------------------------------------------------------
__global__ __launch_bounds__(256) void qkv_gemm(
    const float* __restrict__ x,
    const float* __restrict__ w,
    const float* __restrict__ bias)
{
    __shared__ float As[16][128];   // [k][m]
    __shared__ float Bs[16][64];    // [k][n]

    const int t  = threadIdx.x;
    const int bm = blockIdx.x;      // 0..511
    const int bn = blockIdx.y;      // 0..8

    // A-loader assignment: row am (fixed per thread), 8 contiguous k per chunk
    const int am = t >> 1;
    const int ak = (t & 1) * 8;
    // Shifted-window gather: global row -> (b, gh, gw)
    int mg  = bm * 128 + am;
    int wbv = mg >> 6;
    int n   = mg & 63;
    int b   = wbv >> 8;
    int wh  = (wbv >> 4) & 15;
    int ww  = wbv & 15;
    int gh  = (wh * 8 + (n >> 3) + 4) & 127;
    int gw  = (ww * 8 + (n & 7) + 4) & 127;
    const float* arow = x + ((size_t)((b * 128 + gh) * 128 + gw)) * CD;

    // B-loader assignment
    const int bk  = t >> 4;          // 0..15
    const int bno = (t & 15) * 4;

    const int ty = t >> 4;           // 0..15 -> 8 rows each
    const int tx = t & 15;           // 0..15 -> 4 cols each

    float acc[8][4] = {};

    for (int k0 = 0; k0 < CD; k0 += 16) {
        float4 a0 = *(const float4*)(arow + k0 + ak);
        float4 a1 = *(const float4*)(arow + k0 + ak + 4);
        As[ak + 0][am] = a0.x; As[ak + 1][am] = a0.y;
        As[ak + 2][am] = a0.z; As[ak + 3][am] = a0.w;
        As[ak + 4][am] = a1.x; As[ak + 5][am] = a1.y;
        As[ak + 6][am] = a1.z; As[ak + 7][am] = a1.w;
        *(float4*)&Bs[bk][bno] =
            *(const float4*)(w + (size_t)(k0 + bk) * C3 + bn * 64 + bno);
        __syncthreads();

        #pragma unroll
        for (int kk = 0; kk < 16; kk++) {
            float4 av0 = *(const float4*)&As[kk][ty * 8];
            float4 av1 = *(const float4*)&As[kk][ty * 8 + 4];
            float4 bv  = *(const float4*)&Bs[kk][tx * 4];
            float a8[8] = {av0.x, av0.y, av0.z, av0.w, av1.x, av1.y, av1.z, av1.w};
            float b4[4] = {bv.x, bv.y, bv.z, bv.w};
            #pragma unroll
            for (int ii = 0; ii < 8; ii++)
                #pragma unroll
                for (int jj = 0; jj < 4; jj++)
                    acc[ii][jj] = fmaf(a8[ii], b4[jj], acc[ii][jj]);
        }
        __syncthreads();
    }

    const int col = bn * 64 + tx * 4;
    float4 bb = *(const float4*)(bias + col);
    #pragma unroll
    for (int ii = 0; ii < 8; ii++) {
        int m = bm * 128 + ty * 8 + ii;
        float4 o;
        o.x = acc[ii][0] + bb.x;
        o.y = acc[ii][1] + bb.y;
        o.z = acc[ii][2] + bb.z;
        o.w = acc[ii][3] + bb.w;
        *(float4*)(g_qkv + (size_t)m * C3 + col) = o;
    }
}

// ---------------------------------------------------------------------------
// Kernel 2: per-window LePE + gated attention + softmax + attn@V + proj.
//   grid = 1024 (one window per block), 256 threads, dynamic smem 139264 B.
// ---------------------------------------------------------------------------
__global__ __launch_bounds__(256) void attn_kernel(
    const float* __restrict__ prev,
    const float* __restrict__ lepe_w,
    const float* __restrict__ lepe_b,
    const float* __restrict__ proj_w,
    const float* __restrict__ proj_b,
    float* __restrict__ out)
{
    extern __shared__ float sm[];
    float* sv2 = sm;            // 12288  : v + lepe(v)
    float* so  = sm + 12288;    // 12288  : raw v, then attention output accum
    float* ssc = sm + 24576;    // 4096   : scores / softmax; reused for proj_w tile
    float* sq  = sm + 28672;    // 2112   : q head tile (stride 33)
    float* sk  = sm + 30784;    // 2112   : k head tile (stride 33)
    float* swb = sm + 32896;    // 1728   : lepe weights
    float* slb = sm + 34624;    // 192    : lepe bias
    // total 34816 floats = 139264 bytes

    const int t  = threadIdx.x;
    const int wb = blockIdx.x;
    const float* qb = g_qkv + (size_t)wb * NTOK * C3;
    float* attn_out = out + OUT_ELEMS;

    // ---- load raw V window (64 x 192) + lepe params ----
    for (int idx = t; idx < NTOK * CD; idx += 256) {
        int nn = idx / CD, c = idx - nn * CD;
        so[idx] = qb[nn * C3 + 2 * CD + c];
    }
    for (int idx = t; idx < 9 * CD; idx += 256) swb[idx] = lepe_w[idx];
    if (t < CD) slb[t] = lepe_b[t];
    __syncthreads();

    // ---- LePE: depthwise 3x3, zero-padded within the 8x8 window ----
    for (int idx = t; idx < NTOK * CD; idx += 256) {
        int nn = idx / CD, c = idx - nn * CD;
        int i = nn >> 3, j = nn & 7;
        float a = slb[c];
        #pragma unroll
        for (int kh = 0; kh < 3; kh++) {
            int ii = i + kh - 1;
            if ((unsigned)ii >= 8u) continue;
            #pragma unroll
            for (int kw = 0; kw < 3; kw++) {
                int jj = j + kw - 1;
                if ((unsigned)jj < 8u)
                    a = fmaf(so[(ii * 8 + jj) * CD + c], swb[(kh * 3 + kw) * CD + c], a);
            }
        }
        sv2[idx] = so[idx] + a;
    }

    const int ty = t >> 4, tx = t & 15;
    const int warp = t >> 5, lane = t & 31;

    // ---- per-head attention ----
    for (int h = 0; h < 6; h++) {
        __syncthreads();   // protects sq/sk (prev head) and ssc (prev head's AV)
        for (int idx = t; idx < 2048; idx += 256) {
            int nn = idx >> 5, d = idx & 31;
            sq[nn * 33 + d] = qb[nn * C3 + h * 32 + d] * ATTN_SCALE;
            sk[nn * 33 + d] = qb[nn * C3 + CD + h * 32 + d];
        }
        __syncthreads();

        // scores: 64x64, 4x4 per thread, K=32
        float acc[4][4] = {};
        #pragma unroll
        for (int d = 0; d < 32; d++) {
            float av[4], bv[4];
            #pragma unroll
            for (int ii = 0; ii < 4; ii++) av[ii] = sq[(ty * 4 + ii) * 33 + d];
            #pragma unroll
            for (int jj = 0; jj < 4; jj++) bv[jj] = sk[(tx * 4 + jj) * 33 + d];
            #pragma unroll
            for (int ii = 0; ii < 4; ii++)
                #pragma unroll
                for (int jj = 0; jj < 4; jj++)
                    acc[ii][jj] = fmaf(av[ii], bv[jj], acc[ii][jj]);
        }
        // Hadamard gate with prev_attn_map, store to smem
        const float* pr = prev + ((size_t)(wb * 6 + h)) * 4096;
        #pragma unroll
        for (int ii = 0; ii < 4; ii++) {
            int r = ty * 4 + ii;
            float4 p = *(const float4*)(pr + r * 64 + tx * 4);
            float4 o;
            o.x = acc[ii][0] * p.x; o.y = acc[ii][1] * p.y;
            o.z = acc[ii][2] * p.z; o.w = acc[ii][3] * p.w;
            *(float4*)&ssc[r * 64 + tx * 4] = o;
        }
        __syncthreads();

        // softmax: one warp per row (8 rows per warp); also emit attn output
        for (int r = warp; r < 64; r += 8) {
            float x0 = ssc[r * 64 + lane];
            float x1 = ssc[r * 64 + 32 + lane];
            float mx = fmaxf(x0, x1);
            #pragma unroll
            for (int o = 16; o > 0; o >>= 1)
                mx = fmaxf(mx, __shfl_xor_sync(0xffffffffu, mx, o));
            float e0 = expf(x0 - mx), e1 = expf(x1 - mx);
            float s = e0 + e1;
            #pragma unroll
            for (int o = 16; o > 0; o >>= 1)
                s += __shfl_xor_sync(0xffffffffu, s, o);
            float inv = 1.0f / s;
            e0 *= inv; e1 *= inv;
            ssc[r * 64 + lane] = e0;
            ssc[r * 64 + 32 + lane] = e1;
            float* ao = attn_out + (((size_t)(wb * 6 + h)) * 64 + r) * 64;
            ao[lane] = e0;
            ao[lane + 32] = e1;
        }
        __syncthreads();

        // out_h = attn @ v' : 64x32, each warp handles 8 rows x 32 cols
        {
            float oa[8] = {};
            const int r0 = warp * 8;
            #pragma unroll 8
            for (int j2 = 0; j2 < 64; j2++) {
                float vv = sv2[j2 * CD + h * 32 + lane];
                #pragma unroll
                for (int r = 0; r < 8; r++)
                    oa[r] = fmaf(ssc[(r0 + r) * 64 + j2], vv, oa[r]);
            }
            #pragma unroll
            for (int r = 0; r < 8; r++)
                so[(r0 + r) * CD + h * 32 + lane] = oa[r];
        }
    }
    __syncthreads();

    // ---- projection: (64 x 192) @ (192 x 192), K-tiles of 32 staged in smem ----
    float pacc[3][4][4] = {};
    float* pwt = ssc;   // reuse ssc+sq+sk region: needs 6144 floats, have 8320
    for (int k0 = 0; k0 < CD; k0 += 32) {
        __syncthreads();
        #pragma unroll
        for (int q = 0; q < 6; q++) {
            int fid = t + 256 * q;              // < 1536 float4's
            int kk = fid / 48, cc = fid - kk * 48;
            *(float4*)&pwt[kk * CD + cc * 4] =
                *(const float4*)(proj_w + (size_t)(k0 + kk) * CD + cc * 4);
        }
        __syncthreads();
        #pragma unroll 8
        for (int kk = 0; kk < 32; kk++) {
            float av[4];
            #pragma unroll
            for (int ii = 0; ii < 4; ii++)
                av[ii] = so[(ty * 4 + ii) * CD + k0 + kk];
            #pragma unroll
            for (int cb = 0; cb < 3; cb++) {
                float4 wv = *(const float4*)&pwt[kk * CD + cb * 64 + tx * 4];
                #pragma unroll
                for (int ii = 0; ii < 4; ii++) {
                    pacc[cb][ii][0] = fmaf(av[ii], wv.x, pacc[cb][ii][0]);
                    pacc[cb][ii][1] = fmaf(av[ii], wv.y, pacc[cb][ii][1]);
                    pacc[cb][ii][2] = fmaf(av[ii], wv.z, pacc[cb][ii][2]);
                    pacc[cb][ii][3] = fmaf(av[ii], wv.w, pacc[cb][ii][3]);
                }
            }
        }
    }

    // ---- write out with reverse-shift scatter ----
    const int b  = wb >> 8;
    const int wh = (wb >> 4) & 15;
    const int ww = wb & 15;
    #pragma unroll
    for (int ii = 0; ii < 4; ii++) {
        int nn = ty * 4 + ii;
        int gh = (wh * 8 + (nn >> 3) + 4) & 127;
        int gw = (ww * 8 + (nn & 7) + 4) & 127;
        float* orow = out + ((size_t)((b * 128 + gh) * 128 + gw)) * CD;
        #pragma unroll
        for (int cb = 0; cb < 3; cb++) {
            int c0 = cb * 64 + tx * 4;
            float4 pb4 = *(const float4*)(proj_b + c0);
            float4 o;
            o.x = pacc[cb][ii][0] + pb4.x;
            o.y = pacc[cb][ii][1] + pb4.y;
            o.z = pacc[cb][ii][2] + pb4.z;
            o.w = pacc[cb][ii][3] + pb4.w;
            *(float4*)(orow + c0) = o;
        }
    }
}

// ---------------------------------------------------------------------------
// Launch
// ---------------------------------------------------------------------------
extern "C" void kernel_launch(void* const* d_in, const int* in_sizes, int n_in,
                              void* d_out, int out_size)
{
    const float* x      = (const float*)d_in[0];
    const float* prev   = (const float*)d_in[1];
    const float* qkv_w  = (const float*)d_in[2];
    const float* qkv_b  = (const float*)d_in[3];
    const float* proj_w = (const float*)d_in[4];
    const float* proj_b = (const float*)d_in[5];
    const float* lepe_w = (const float*)d_in[6];
    const float* lepe_b = (const float*)d_in[7];
    float* out = (float*)d_out;

    const int smem_bytes = 34816 * 4;   // 139264
    cudaFuncSetAttribute(attn_kernel,
                         cudaFuncAttributeMaxDynamicSharedMemorySize, smem_bytes);

    qkv_gemm<<<dim3(512, 9), 256>>>(x, qkv_w, qkv_b);
    attn_kernel<<<NWIN, 256, smem_bytes>>>(prev, lepe_w, lepe_b,
                                           proj_w, proj_b, out);
}

// round 2
// speedup vs baseline: 1.1847x; 1.1847x over previous
#include <cuda_runtime.h>
#include <math.h>

#define NWIN 1024
#define NTOK 64
#define CD   192
#define C3   576
#define OUT_ELEMS 12582912
#define ATTN_SCALE 0.17677669529663687f

// scratch
static __device__ __align__(16) float g_qkv[NWIN * NTOK * C3];   // 151 MB
static __device__ __align__(16) float g_av [NWIN * NTOK * CD];   // 50 MB

// ---- packed fp32x2 helpers (sm_100+ PTX) ----
__device__ __forceinline__ void ffma2(unsigned long long& d,
                                      unsigned long long a,
                                      unsigned long long b) {
    asm("fma.rn.f32x2 %0, %1, %2, %0;" : "+l"(d) : "l"(a), "l"(b));
}
__device__ __forceinline__ unsigned long long pack2(float lo, float hi) {
    unsigned long long r;
    asm("mov.b64 %0, {%1, %2};" : "=l"(r) : "f"(lo), "f"(hi));
    return r;
}

// ---------------------------------------------------------------------------
// Kernel 1: QKV GEMM, fused shifted-window gather. M=65536, K=192, N=576.
// 128x64 tile, 256 thr, 8x4 microtile done as 4 m-pairs x 4 n via FFMA2.
// ---------------------------------------------------------------------------
__global__ __launch_bounds__(256) void qkv_gemm(
    const float* __restrict__ x,
    const float* __restrict__ w,
    const float* __restrict__ bias)
{
    __shared__ float As[16][128];
    __shared__ float Bs[16][64];

    const int t  = threadIdx.x;
    const int bm = blockIdx.x;
    const int bn = blockIdx.y;

    const int am = t >> 1;
    const int ak = (t & 1) * 8;
    int mg  = bm * 128 + am;
    int wbv = mg >> 6;
    int n   = mg & 63;
    int b   = wbv >> 8;
    int wh  = (wbv >> 4) & 15;
    int ww  = wbv & 15;
    int gh  = (wh * 8 + (n >> 3) + 4) & 127;
    int gw  = (ww * 8 + (n & 7) + 4) & 127;
    const float* arow = x + ((size_t)((b * 128 + gh) * 128 + gw)) * CD;

    const int bk  = t >> 4;
    const int bno = (t & 15) * 4;
    const int ty = t >> 4;
    const int tx = t & 15;

    unsigned long long acc2[4][4] = {};   // [m-pair][n], (0,0) packed zeros

    for (int k0 = 0; k0 < CD; k0 += 16) {
        float4 a0 = *(const float4*)(arow + k0 + ak);
        float4 a1 = *(const float4*)(arow + k0 + ak + 4);
        As[ak + 0][am] = a0.x; As[ak + 1][am] = a0.y;
        As[ak + 2][am] = a0.z; As[ak + 3][am] = a0.w;
        As[ak + 4][am] = a1.x; As[ak + 5][am] = a1.y;
        As[ak + 6][am] = a1.z; As[ak + 7][am] = a1.w;
        *(float4*)&Bs[bk][bno] =
            *(const float4*)(w + (size_t)(k0 + bk) * C3 + bn * 64 + bno);
        __syncthreads();

        #pragma unroll
        for (int kk = 0; kk < 16; kk++) {
            unsigned long long a2[4];
            #pragma unroll
            for (int ip = 0; ip < 4; ip++)
                a2[ip] = *(const unsigned long long*)&As[kk][ty * 8 + 2 * ip];
            float4 bv = *(const float4*)&Bs[kk][tx * 4];
            unsigned long long bs0 = pack2(bv.x, bv.x);
            unsigned long long bs1 = pack2(bv.y, bv.y);
            unsigned long long bs2 = pack2(bv.z, bv.z);
            unsigned long long bs3 = pack2(bv.w, bv.w);
            #pragma unroll
            for (int ip = 0; ip < 4; ip++) {
                ffma2(acc2[ip][0], a2[ip], bs0);
                ffma2(acc2[ip][1], a2[ip], bs1);
                ffma2(acc2[ip][2], a2[ip], bs2);
                ffma2(acc2[ip][3], a2[ip], bs3);
            }
        }
        __syncthreads();
    }

    const int col = bn * 64 + tx * 4;
    float4 bb = *(const float4*)(bias + col);
    #pragma unroll
    for (int ip = 0; ip < 4; ip++) {
        float2 c0 = *(float2*)&acc2[ip][0];
        float2 c1 = *(float2*)&acc2[ip][1];
        float2 c2 = *(float2*)&acc2[ip][2];
        float2 c3 = *(float2*)&acc2[ip][3];
        int m0 = bm * 128 + ty * 8 + 2 * ip;
        float4 o0 = {c0.x + bb.x, c1.x + bb.y, c2.x + bb.z, c3.x + bb.w};
        float4 o1 = {c0.y + bb.x, c1.y + bb.y, c2.y + bb.z, c3.y + bb.w};
        *(float4*)(g_qkv + (size_t)m0 * C3 + col)       = o0;
        *(float4*)(g_qkv + (size_t)(m0 + 1) * C3 + col) = o1;
    }
}

// ---------------------------------------------------------------------------
// Kernel 2: LePE + gated attention + softmax + attn@V.
// grid=1024, 384 thr (12 warps). warp w -> head w/2, half w&1.
// Lane owns one query row: scores in 64 regs, softmax reg-local, no shuffles.
// ---------------------------------------------------------------------------
__global__ __launch_bounds__(384, 1) void attn2(
    const float* __restrict__ prev,
    const float* __restrict__ lepe_w,
    const float* __restrict__ lepe_b,
    float* __restrict__ out)
{
    extern __shared__ float sm[];
    float* sv2 = sm;            // 12288 : v + lepe(v)       [n][c]
    float* sqT = sm + 12288;    // 12480 : q^T per head      [h][d][65]
    float* skT = sm + 24768;    // 13056 : raw v, then k^T   [h][d][68]
    float* swb = sm + 37824;    // 1728
    float* slb = sm + 39552;    // 192   -> total 39744 floats = 158976 B

    const int t  = threadIdx.x;
    const int wb = blockIdx.x;
    const float* qb = g_qkv + (size_t)wb * NTOK * C3;

    // load raw v (into skT region, flat) + q transposed (scaled) + lepe params
    for (int idx = t; idx < NTOK * CD; idx += 384) {
        int n = idx / CD, c = idx - n * CD;
        skT[idx] = qb[n * C3 + 2 * CD + c];
        int h = c >> 5, d = c & 31;
        sqT[h * 2080 + d * 65 + n] = qb[n * C3 + c] * ATTN_SCALE;
    }
    for (int idx = t; idx < 9 * CD; idx += 384) swb[idx] = lepe_w[idx];
    if (t < CD) slb[t] = lepe_b[t];
    __syncthreads();

    // LePE depthwise 3x3 within the 8x8 window
    for (int idx = t; idx < NTOK * CD; idx += 384) {
        int n = idx / CD, c = idx - n * CD;
        int i = n >> 3, j = n & 7;
        float a = slb[c];
        #pragma unroll
        for (int kh = 0; kh < 3; kh++) {
            int ii = i + kh - 1;
            if ((unsigned)ii >= 8u) continue;
            #pragma unroll
            for (int kw = 0; kw < 3; kw++) {
                int jj = j + kw - 1;
                if ((unsigned)jj < 8u)
                    a = fmaf(skT[(ii * 8 + jj) * CD + c],
                             swb[(kh * 3 + kw) * CD + c], a);
            }
        }
        sv2[idx] = skT[idx] + a;
    }
    __syncthreads();

    // load k transposed (overwrites raw v)
    for (int idx = t; idx < NTOK * CD; idx += 384) {
        int n = idx / CD, c = idx - n * CD;
        int h = c >> 5, d = c & 31;
        skT[h * 2176 + d * 68 + n] = qb[n * C3 + CD + c];
    }
    __syncthreads();

    const int w    = t >> 5;
    const int lane = t & 31;
    const int h    = w >> 1;
    const int r    = ((w & 1) << 5) | lane;
    const float* qh = sqT + h * 2080;
    const float* kh = skT + h * 2176;

    // scores: row r vs all 64 keys, j-pairs packed
    float2 sc[32];
    #pragma unroll
    for (int i = 0; i < 32; i++) sc[i] = make_float2(0.f, 0.f);
    for (int d = 0; d < 32; d++) {
        float qv = qh[d * 65 + r];
        unsigned long long qs = pack2(qv, qv);
        const unsigned long long* kd = (const unsigned long long*)(kh + d * 68);
        #pragma unroll
        for (int jp = 0; jp < 32; jp++)
            ffma2(*(unsigned long long*)&sc[jp], qs, kd[jp]);
    }

    float* p = (float*)sc;   // 64 scores

    // Hadamard gate with prev_attn_map
    const float* pr = prev + (((size_t)(wb * 6 + h)) * 64 + r) * 64;
    #pragma unroll
    for (int i = 0; i < 16; i++) {
        float4 pv = ((const float4*)pr)[i];
        p[4*i+0] *= pv.x; p[4*i+1] *= pv.y; p[4*i+2] *= pv.z; p[4*i+3] *= pv.w;
    }

    // softmax (register-local)
    float mx = p[0];
    #pragma unroll
    for (int i = 1; i < 64; i++) mx = fmaxf(mx, p[i]);
    float s = 0.f;
    #pragma unroll
    for (int i = 0; i < 64; i++) { p[i] = __expf(p[i] - mx); s += p[i]; }
    float inv = 1.0f / s;

    float* ao = out + OUT_ELEMS + (((size_t)(wb * 6 + h)) * 64 + r) * 64;
    #pragma unroll
    for (int i = 0; i < 16; i++) {
        float4 o;
        o.x = p[4*i+0] * inv; o.y = p[4*i+1] * inv;
        o.z = p[4*i+2] * inv; o.w = p[4*i+3] * inv;
        p[4*i+0] = o.x; p[4*i+1] = o.y; p[4*i+2] = o.z; p[4*i+3] = o.w;
        ((float4*)ao)[i] = o;
    }

    // attn @ v' : out row (32 dims) for this head
    float2 o2[16];
    #pragma unroll
    for (int i = 0; i < 16; i++) o2[i] = make_float2(0.f, 0.f);
    for (int j = 0; j < 64; j++) {
        unsigned long long ps = pack2(p[j], p[j]);
        const unsigned long long* vr =
            (const unsigned long long*)(sv2 + j * CD + h * 32);
        #pragma unroll
        for (int dp = 0; dp < 16; dp++)
            ffma2(*(unsigned long long*)&o2[dp], ps, vr[dp]);
    }
    float* op = g_av + ((size_t)(wb * 64 + r)) * CD + h * 32;
    #pragma unroll
    for (int i = 0; i < 8; i++)
        ((float4*)op)[i] = ((float4*)o2)[i];
}

// ---------------------------------------------------------------------------
// Kernel 3: projection GEMM (65536 x 192 @ 192 x 192) + bias,
// fused reverse-shift window scatter.
// ---------------------------------------------------------------------------
__global__ __launch_bounds__(256) void proj_gemm(
    const float* __restrict__ w,
    const float* __restrict__ bias,
    float* __restrict__ out)
{
    __shared__ float As[16][128];
    __shared__ float Bs[16][64];

    const int t  = threadIdx.x;
    const int bm = blockIdx.x;
    const int bn = blockIdx.y;

    const int am = t >> 1;
    const int ak = (t & 1) * 8;
    const float* arow = g_av + (size_t)(bm * 128 + am) * CD;

    const int bk  = t >> 4;
    const int bno = (t & 15) * 4;
    const int ty = t >> 4;
    const int tx = t & 15;

    unsigned long long acc2[4][4] = {};

    for (int k0 = 0; k0 < CD; k0 += 16) {
        float4 a0 = *(const float4*)(arow + k0 + ak);
        float4 a1 = *(const float4*)(arow + k0 + ak + 4);
        As[ak + 0][am] = a0.x; As[ak + 1][am] = a0.y;
        As[ak + 2][am] = a0.z; As[ak + 3][am] = a0.w;
        As[ak + 4][am] = a1.x; As[ak + 5][am] = a1.y;
        As[ak + 6][am] = a1.z; As[ak + 7][am] = a1.w;
        *(float4*)&Bs[bk][bno] =
            *(const float4*)(w + (size_t)(k0 + bk) * CD + bn * 64 + bno);
        __syncthreads();

        #pragma unroll
        for (int kk = 0; kk < 16; kk++) {
            unsigned long long a2[4];
            #pragma unroll
            for (int ip = 0; ip < 4; ip++)
                a2[ip] = *(const unsigned long long*)&As[kk][ty * 8 + 2 * ip];
            float4 bv = *(const float4*)&Bs[kk][tx * 4];
            unsigned long long bs0 = pack2(bv.x, bv.x);
            unsigned long long bs1 = pack2(bv.y, bv.y);
            unsigned long long bs2 = pack2(bv.z, bv.z);
            unsigned long long bs3 = pack2(bv.w, bv.w);
            #pragma unroll
            for (int ip = 0; ip < 4; ip++) {
                ffma2(acc2[ip][0], a2[ip], bs0);
                ffma2(acc2[ip][1], a2[ip], bs1);
                ffma2(acc2[ip][2], a2[ip], bs2);
                ffma2(acc2[ip][3], a2[ip], bs3);
            }
        }
        __syncthreads();
    }

    const int col = bn * 64 + tx * 4;
    float4 bb = *(const float4*)(bias + col);
    #pragma unroll
    for (int ip = 0; ip < 4; ip++) {
        float2 c0 = *(float2*)&acc2[ip][0];
        float2 c1 = *(float2*)&acc2[ip][1];
        float2 c2 = *(float2*)&acc2[ip][2];
        float2 c3 = *(float2*)&acc2[ip][3];
        #pragma unroll
        for (int half = 0; half < 2; half++) {
            int m = bm * 128 + ty * 8 + 2 * ip + half;
            int wbv = m >> 6, n = m & 63;
            int b  = wbv >> 8;
            int wh = (wbv >> 4) & 15;
            int ww = wbv & 15;
            int gh = (wh * 8 + (n >> 3) + 4) & 127;
            int gw = (ww * 8 + (n & 7) + 4) & 127;
            float4 o;
            if (half == 0) { o = make_float4(c0.x + bb.x, c1.x + bb.y, c2.x + bb.z, c3.x + bb.w); }
            else           { o = make_float4(c0.y + bb.x, c1.y + bb.y, c2.y + bb.z, c3.y + bb.w); }
            *(float4*)(out + ((size_t)((b * 128 + gh) * 128 + gw)) * CD + col) = o;
        }
    }
}

// ---------------------------------------------------------------------------
extern "C" void kernel_launch(void* const* d_in, const int* in_sizes, int n_in,
                              void* d_out, int out_size)
{
    const float* x      = (const float*)d_in[0];
    const float* prev   = (const float*)d_in[1];
    const float* qkv_w  = (const float*)d_in[2];
    const float* qkv_b  = (const float*)d_in[3];
    const float* proj_w = (const float*)d_in[4];
    const float* proj_b = (const float*)d_in[5];
    const float* lepe_w = (const float*)d_in[6];
    const float* lepe_b = (const float*)d_in[7];
    float* out = (float*)d_out;

    const int smem_bytes = 39744 * 4;   // 158976
    cudaFuncSetAttribute(attn2,
                         cudaFuncAttributeMaxDynamicSharedMemorySize, smem_bytes);

    qkv_gemm<<<dim3(512, 9), 256>>>(x, qkv_w, qkv_b);
    attn2<<<NWIN, 384, smem_bytes>>>(prev, lepe_w, lepe_b, out);
    proj_gemm<<<dim3(512, 3), 256>>>(proj_w, proj_b, out);
}

// round 7
// speedup vs baseline: 1.4276x; 1.2050x over previous
#include <cuda_runtime.h>
#include <cuda_bf16.h>
#include <math.h>
#include <stdint.h>

#define NWIN 1024
#define NTOK 64
#define CD   192
#define C3   576
#define OUT_ELEMS 12582912
#define ATTN_SCALE 0.17677669529663687f

// ---------------- device scratch ----------------
static __device__ __align__(16) float g_qkv[NWIN * NTOK * C3];   // 151 MB
static __device__ __align__(16) float g_av [NWIN * NTOK * CD];   // 50 MB
static __device__ __align__(16) __nv_bfloat16 g_wt_hi[C3 * CD];  // qkv_w^T hi
static __device__ __align__(16) __nv_bfloat16 g_wt_lo[C3 * CD];
static __device__ __align__(16) __nv_bfloat16 g_pt_hi[CD * CD];  // proj_w^T hi
static __device__ __align__(16) __nv_bfloat16 g_pt_lo[CD * CD];

// ---------------- PTX helpers ----------------
__device__ __forceinline__ void ffma2(unsigned long long& d,
                                      unsigned long long a,
                                      unsigned long long b) {
    asm("fma.rn.f32x2 %0, %1, %2, %0;" : "+l"(d) : "l"(a), "l"(b));
}
__device__ __forceinline__ unsigned long long pack2(float lo, float hi) {
    unsigned long long r;
    asm("mov.b64 %0, {%1, %2};" : "=l"(r) : "f"(lo), "f"(hi));
    return r;
}
__device__ __forceinline__ void mma_bf16(float* c, const uint32_t* a,
                                         const uint32_t* b) {
    asm volatile(
        "mma.sync.aligned.m16n8k16.row.col.f32.bf16.bf16.f32 "
        "{%0,%1,%2,%3}, {%4,%5,%6,%7}, {%8,%9}, {%0,%1,%2,%3};"
        : "+f"(c[0]), "+f"(c[1]), "+f"(c[2]), "+f"(c[3])
        : "r"(a[0]), "r"(a[1]), "r"(a[2]), "r"(a[3]), "r"(b[0]), "r"(b[1]));
}

// ---------------------------------------------------------------------------
// Kernel 0: pre-transpose + bf16 hi/lo split of weight matrices.
// ---------------------------------------------------------------------------
__global__ __launch_bounds__(256) void prep_w(const float* __restrict__ qkv_w,
                                              const float* __restrict__ proj_w)
{
    int idx = blockIdx.x * 256 + threadIdx.x;
    if (idx < C3 * CD) {
        int n = idx / CD, k = idx - n * CD;
        float v = qkv_w[k * C3 + n];
        __nv_bfloat16 h = __float2bfloat16_rn(v);
        g_wt_hi[idx] = h;
        g_wt_lo[idx] = __float2bfloat16_rn(v - __bfloat162float(h));
    } else {
        int j = idx - C3 * CD;
        if (j < CD * CD) {
            int n = j / CD, k = j - n * CD;
            float v = proj_w[k * CD + n];
            __nv_bfloat16 h = __float2bfloat16_rn(v);
            g_pt_hi[j] = h;
            g_pt_lo[j] = __float2bfloat16_rn(v - __bfloat162float(h));
        }
    }
}

// ---------------------------------------------------------------------------
// bf16x3 mma.sync GEMM, fragments loaded with plain LDS (no ldmatrix).
// Block tile 128(M) x 64(N), K=192 in 3 chunks of 64.
// 8 warps = 4m x 2n, warp tile 32x32, mma m16n8k16.
// PROJ mode reads g_av via the device symbol (NOT a host-passed pointer).
// ---------------------------------------------------------------------------
#define OFF_AH 0
#define OFF_AL 18432
#define OFF_BH 36864
#define OFF_BL 62464
#define MM_SMEM 88064

template<bool QKV>
__global__ __launch_bounds__(256, 2) void mma_gemm(
    const float* __restrict__ x_in,      // used only in QKV mode
    const float* __restrict__ bias,
    float* __restrict__ outp)            // used only in PROJ mode
{
    extern __shared__ char sm[];
    float* stage = (float*)sm;           // reused after compute

    const float* a_src = QKV ? x_in : (const float*)g_av;   // device-side symbol

    const int t    = threadIdx.x;
    const int w    = t >> 5;
    const int lane = t & 31;
    const int bm   = blockIdx.x;
    const int bn   = blockIdx.y;
    const int wm   = w >> 1;             // 0..3
    const int wn   = w & 1;              // 0..1
    const int g    = lane >> 2;          // mma groupID 0..7
    const int tg   = lane & 3;           // thread-in-group

    // ---- load B tile (64 n-rows, full K=192) hi+lo, once ----
    {
        const uint4* srch = (const uint4*)(QKV ? g_wt_hi : g_pt_hi);
        const uint4* srcl = (const uint4*)(QKV ? g_wt_lo : g_pt_lo);
        #pragma unroll
        for (int i = 0; i < 6; i++) {
            int idx = t + 256 * i;               // < 1536
            int row = idx / 24, c16 = idx - row * 24;
            uint32_t dst = (uint32_t)(row * 400 + c16 * 16);
            int src = (bn * 64 + row) * 24 + c16;
            *(uint4*)(sm + OFF_BH + dst) = srch[src];
            *(uint4*)(sm + OFF_BL + dst) = srcl[src];
        }
    }

    // ---- A source row (gather for QKV) ----
    const int arow_l = t >> 1;           // 0..127
    const int seg    = t & 1;            // 32-float half of 64-chunk
    const float* arow;
    {
        int gm = bm * 128 + arow_l;
        if (QKV) {
            int wbv = gm >> 6, n = gm & 63;
            int b  = wbv >> 8;
            int wh = (wbv >> 4) & 15;
            int ww = wbv & 15;
            int gh = (wh * 8 + (n >> 3) + 4) & 127;
            int gw = (ww * 8 + (n & 7) + 4) & 127;
            arow = a_src + ((size_t)((b * 128 + gh) * 128 + gw)) * CD;
        } else {
            arow = a_src + (size_t)gm * CD;
        }
    }
    const uint32_t a_sts = (uint32_t)(arow_l * 144 + seg * 64);

    float acc[2][4][4] = {};

    for (int c = 0; c < 3; c++) {
        const int k0 = c * 64;
        const uint32_t bko = (uint32_t)(c * 128);   // B chunk byte offset
        __syncthreads();
        // ---- A chunk: load fp32, split to bf16 hi/lo, store ----
        #pragma unroll
        for (int j = 0; j < 8; j++) {
            float4 v = *(const float4*)(arow + k0 + seg * 32 + j * 4);
            __nv_bfloat162 h01 = __float22bfloat162_rn(make_float2(v.x, v.y));
            __nv_bfloat162 h23 = __float22bfloat162_rn(make_float2(v.z, v.w));
            float2 f01 = __bfloat1622float2(h01);
            float2 f23 = __bfloat1622float2(h23);
            __nv_bfloat162 l01 = __float22bfloat162_rn(
                make_float2(v.x - f01.x, v.y - f01.y));
            __nv_bfloat162 l23 = __float22bfloat162_rn(
                make_float2(v.z - f23.x, v.w - f23.y));
            uint2 hh, ll;
            hh.x = *(uint32_t*)&h01; hh.y = *(uint32_t*)&h23;
            ll.x = *(uint32_t*)&l01; ll.y = *(uint32_t*)&l23;
            *(uint2*)(sm + OFF_AH + a_sts + j * 8) = hh;
            *(uint2*)(sm + OFF_AL + a_sts + j * 8) = ll;
        }
        __syncthreads();

        // ---- compute: 4 k-steps of 16, fragments via direct LDS ----
        #pragma unroll
        for (int ks = 0; ks < 4; ks++) {
            const uint32_t kb = (uint32_t)(ks * 32 + tg * 4);

            uint32_t Ah[2][4], Al[2][4];
            #pragma unroll
            for (int i = 0; i < 2; i++) {
                const uint32_t ab = (uint32_t)((wm * 32 + i * 16 + g) * 144) + kb;
                Ah[i][0] = *(const uint32_t*)(sm + OFF_AH + ab);
                Ah[i][1] = *(const uint32_t*)(sm + OFF_AH + ab + 8 * 144);
                Ah[i][2] = *(const uint32_t*)(sm + OFF_AH + ab + 16);
                Ah[i][3] = *(const uint32_t*)(sm + OFF_AH + ab + 8 * 144 + 16);
                Al[i][0] = *(const uint32_t*)(sm + OFF_AL + ab);
                Al[i][1] = *(const uint32_t*)(sm + OFF_AL + ab + 8 * 144);
                Al[i][2] = *(const uint32_t*)(sm + OFF_AL + ab + 16);
                Al[i][3] = *(const uint32_t*)(sm + OFF_AL + ab + 8 * 144 + 16);
            }
            uint32_t Bh[4][2], Bl[4][2];
            #pragma unroll
            for (int j = 0; j < 4; j++) {
                const uint32_t bb =
                    (uint32_t)((wn * 32 + j * 8 + g) * 400) + bko + kb;
                Bh[j][0] = *(const uint32_t*)(sm + OFF_BH + bb);
                Bh[j][1] = *(const uint32_t*)(sm + OFF_BH + bb + 16);
                Bl[j][0] = *(const uint32_t*)(sm + OFF_BL + bb);
                Bl[j][1] = *(const uint32_t*)(sm + OFF_BL + bb + 16);
            }
            #pragma unroll
            for (int i = 0; i < 2; i++)
                #pragma unroll
                for (int j = 0; j < 4; j++) {
                    mma_bf16(acc[i][j], Ah[i], Bh[j]);
                    mma_bf16(acc[i][j], Ah[i], Bl[j]);
                    mma_bf16(acc[i][j], Al[i], Bh[j]);
                }
        }
    }
    __syncthreads();

    // ---- stage C to smem (stride 68 floats) ----
    #pragma unroll
    for (int i = 0; i < 2; i++) {
        int row0 = wm * 32 + i * 16 + g;
        #pragma unroll
        for (int j = 0; j < 4; j++) {
            int col = wn * 32 + j * 8 + 2 * tg;
            *(float2*)&stage[row0 * 68 + col] =
                make_float2(acc[i][j][0], acc[i][j][1]);
            *(float2*)&stage[(row0 + 8) * 68 + col] =
                make_float2(acc[i][j][2], acc[i][j][3]);
        }
    }
    __syncthreads();

    // ---- coalesced store with bias (+ scatter for PROJ) ----
    const int s = t & 15;
    float4 b4 = *(const float4*)(bias + bn * 64 + s * 4);
    #pragma unroll
    for (int it = 0; it < 8; it++) {
        int row = (t >> 4) + 16 * it;
        float4 v = *(float4*)&stage[row * 68 + s * 4];
        v.x += b4.x; v.y += b4.y; v.z += b4.z; v.w += b4.w;
        if (QKV) {
            *(float4*)(g_qkv + (size_t)(bm * 128 + row) * C3 + bn * 64 + s * 4) = v;
        } else {
            int m = bm * 128 + row;
            int wbv = m >> 6, n = m & 63;
            int b  = wbv >> 8;
            int wh = (wbv >> 4) & 15;
            int ww = wbv & 15;
            int gh = (wh * 8 + (n >> 3) + 4) & 127;
            int gw = (ww * 8 + (n & 7) + 4) & 127;
            *(float4*)(outp + ((size_t)((b * 128 + gh) * 128 + gw)) * CD
                       + bn * 64 + s * 4) = v;
        }
    }
}

// ---------------------------------------------------------------------------
// Kernel 2: LePE + gated attention + softmax + attn@V.  (unchanged, passing)
// ---------------------------------------------------------------------------
__global__ __launch_bounds__(384, 1) void attn2(
    const float* __restrict__ prev,
    const float* __restrict__ lepe_w,
    const float* __restrict__ lepe_b,
    float* __restrict__ out)
{
    extern __shared__ float smf[];
    float* sv2 = smf;
    float* sqT = smf + 12288;
    float* skT = smf + 24768;
    float* swb = smf + 37824;
    float* slb = smf + 39552;

    const int t  = threadIdx.x;
    const int wb = blockIdx.x;
    const float* qb = g_qkv + (size_t)wb * NTOK * C3;

    for (int idx = t; idx < NTOK * CD; idx += 384) {
        int n = idx / CD, c = idx - n * CD;
        skT[idx] = qb[n * C3 + 2 * CD + c];
        int h = c >> 5, d = c & 31;
        sqT[h * 2080 + d * 65 + n] = qb[n * C3 + c] * ATTN_SCALE;
    }
    for (int idx = t; idx < 9 * CD; idx += 384) swb[idx] = lepe_w[idx];
    if (t < CD) slb[t] = lepe_b[t];
    __syncthreads();

    for (int idx = t; idx < NTOK * CD; idx += 384) {
        int n = idx / CD, c = idx - n * CD;
        int i = n >> 3, j = n & 7;
        float a = slb[c];
        #pragma unroll
        for (int kh = 0; kh < 3; kh++) {
            int ii = i + kh - 1;
            if ((unsigned)ii >= 8u) continue;
            #pragma unroll
            for (int kw = 0; kw < 3; kw++) {
                int jj = j + kw - 1;
                if ((unsigned)jj < 8u)
                    a = fmaf(skT[(ii * 8 + jj) * CD + c],
                             swb[(kh * 3 + kw) * CD + c], a);
            }
        }
        sv2[idx] = skT[idx] + a;
    }
    __syncthreads();

    for (int idx = t; idx < NTOK * CD; idx += 384) {
        int n = idx / CD, c = idx - n * CD;
        int h = c >> 5, d = c & 31;
        skT[h * 2176 + d * 68 + n] = qb[n * C3 + CD + c];
    }
    __syncthreads();

    const int w    = t >> 5;
    const int lane = t & 31;
    const int h    = w >> 1;
    const int r    = ((w & 1) << 5) | lane;
    const float* qh = sqT + h * 2080;
    const float* kh = skT + h * 2176;

    float2 sc[32];
    #pragma unroll
    for (int i = 0; i < 32; i++) sc[i] = make_float2(0.f, 0.f);
    for (int d = 0; d < 32; d++) {
        float qv = qh[d * 65 + r];
        unsigned long long qs = pack2(qv, qv);
        const unsigned long long* kd = (const unsigned long long*)(kh + d * 68);
        #pragma unroll
        for (int jp = 0; jp < 32; jp++)
            ffma2(*(unsigned long long*)&sc[jp], qs, kd[jp]);
    }

    float* p = (float*)sc;
    const float* pr = prev + (((size_t)(wb * 6 + h)) * 64 + r) * 64;
    #pragma unroll
    for (int i = 0; i < 16; i++) {
        float4 pv = ((const float4*)pr)[i];
        p[4*i+0] *= pv.x; p[4*i+1] *= pv.y; p[4*i+2] *= pv.z; p[4*i+3] *= pv.w;
    }

    float mx = p[0];
    #pragma unroll
    for (int i = 1; i < 64; i++) mx = fmaxf(mx, p[i]);
    float s = 0.f;
    #pragma unroll
    for (int i = 0; i < 64; i++) { p[i] = __expf(p[i] - mx); s += p[i]; }
    float inv = 1.0f / s;

    float* ao = out + OUT_ELEMS + (((size_t)(wb * 6 + h)) * 64 + r) * 64;
    #pragma unroll
    for (int i = 0; i < 16; i++) {
        float4 o;
        o.x = p[4*i+0] * inv; o.y = p[4*i+1] * inv;
        o.z = p[4*i+2] * inv; o.w = p[4*i+3] * inv;
        p[4*i+0] = o.x; p[4*i+1] = o.y; p[4*i+2] = o.z; p[4*i+3] = o.w;
        ((float4*)ao)[i] = o;
    }

    float2 o2[16];
    #pragma unroll
    for (int i = 0; i < 16; i++) o2[i] = make_float2(0.f, 0.f);
    for (int j = 0; j < 64; j++) {
        unsigned long long ps = pack2(p[j], p[j]);
        const unsigned long long* vr =
            (const unsigned long long*)(sv2 + j * CD + h * 32);
        #pragma unroll
        for (int dp = 0; dp < 16; dp++)
            ffma2(*(unsigned long long*)&o2[dp], ps, vr[dp]);
    }
    float* op = g_av + ((size_t)(wb * 64 + r)) * CD + h * 32;
    #pragma unroll
    for (int i = 0; i < 8; i++)
        ((float4*)op)[i] = ((float4*)o2)[i];
}

// ---------------------------------------------------------------------------
extern "C" void kernel_launch(void* const* d_in, const int* in_sizes, int n_in,
                              void* d_out, int out_size)
{
    const float* x      = (const float*)d_in[0];
    const float* prev   = (const float*)d_in[1];
    const float* qkv_w  = (const float*)d_in[2];
    const float* qkv_b  = (const float*)d_in[3];
    const float* proj_w = (const float*)d_in[4];
    const float* proj_b = (const float*)d_in[5];
    const float* lepe_w = (const float*)d_in[6];
    const float* lepe_b = (const float*)d_in[7];
    float* out = (float*)d_out;

    const int attn_smem = 39744 * 4;
    cudaFuncSetAttribute(attn2,
                         cudaFuncAttributeMaxDynamicSharedMemorySize, attn_smem);
    cudaFuncSetAttribute(mma_gemm<true>,
                         cudaFuncAttributeMaxDynamicSharedMemorySize, MM_SMEM);
    cudaFuncSetAttribute(mma_gemm<false>,
                         cudaFuncAttributeMaxDynamicSharedMemorySize, MM_SMEM);

    prep_w<<<576, 256>>>(qkv_w, proj_w);
    mma_gemm<true><<<dim3(512, 9), 256, MM_SMEM>>>(x, qkv_b, nullptr);
    attn2<<<NWIN, 384, attn_smem>>>(prev, lepe_w, lepe_b, out);
    mma_gemm<false><<<dim3(512, 3), 256, MM_SMEM>>>(nullptr, proj_b, out);
}

// round 8
// speedup vs baseline: 1.4955x; 1.0476x over previous
#include <cuda_runtime.h>
#include <cuda_bf16.h>
#include <math.h>
#include <stdint.h>

#define NWIN 1024
#define NTOK 64
#define CD   192
#define C3   576
#define NROW 65536               // NWIN * NTOK
#define OUT_ELEMS 12582912
#define ATTN_SCALE 0.17677669529663687f

// ---------------- device scratch ----------------
static __device__ __align__(16) float g_qkv[NWIN * NTOK * C3];       // 151 MB
static __device__ __align__(16) __nv_bfloat16 g_xh[NROW * CD];       // 25 MB (gathered x, hi)
static __device__ __align__(16) __nv_bfloat16 g_xl[NROW * CD];
static __device__ __align__(16) __nv_bfloat16 g_avh[NROW * CD];      // attn@V out, hi
static __device__ __align__(16) __nv_bfloat16 g_avl[NROW * CD];
static __device__ __align__(16) __nv_bfloat16 g_wt_hi[C3 * CD];
static __device__ __align__(16) __nv_bfloat16 g_wt_lo[C3 * CD];
static __device__ __align__(16) __nv_bfloat16 g_pt_hi[CD * CD];
static __device__ __align__(16) __nv_bfloat16 g_pt_lo[CD * CD];

// ---------------- PTX helpers ----------------
__device__ __forceinline__ void ffma2(unsigned long long& d,
                                      unsigned long long a,
                                      unsigned long long b) {
    asm("fma.rn.f32x2 %0, %1, %2, %0;" : "+l"(d) : "l"(a), "l"(b));
}
__device__ __forceinline__ unsigned long long pack2(float lo, float hi) {
    unsigned long long r;
    asm("mov.b64 %0, {%1, %2};" : "=l"(r) : "f"(lo), "f"(hi));
    return r;
}
__device__ __forceinline__ void mma_bf16(float* c, const uint32_t* a,
                                         const uint32_t* b) {
    asm volatile(
        "mma.sync.aligned.m16n8k16.row.col.f32.bf16.bf16.f32 "
        "{%0,%1,%2,%3}, {%4,%5,%6,%7}, {%8,%9}, {%0,%1,%2,%3};"
        : "+f"(c[0]), "+f"(c[1]), "+f"(c[2]), "+f"(c[3])
        : "r"(a[0]), "r"(a[1]), "r"(a[2]), "r"(a[3]), "r"(b[0]), "r"(b[1]));
}

// ---------------------------------------------------------------------------
// Kernel 0a: weight pre-transpose + bf16 hi/lo split.
// ---------------------------------------------------------------------------
__global__ __launch_bounds__(256) void prep_w(const float* __restrict__ qkv_w,
                                              const float* __restrict__ proj_w)
{
    int idx = blockIdx.x * 256 + threadIdx.x;
    if (idx < C3 * CD) {
        int n = idx / CD, k = idx - n * CD;
        float v = qkv_w[k * C3 + n];
        __nv_bfloat16 h = __float2bfloat16_rn(v);
        g_wt_hi[idx] = h;
        g_wt_lo[idx] = __float2bfloat16_rn(v - __bfloat162float(h));
    } else {
        int j = idx - C3 * CD;
        if (j < CD * CD) {
            int n = j / CD, k = j - n * CD;
            float v = proj_w[k * CD + n];
            __nv_bfloat16 h = __float2bfloat16_rn(v);
            g_pt_hi[j] = h;
            g_pt_lo[j] = __float2bfloat16_rn(v - __bfloat162float(h));
        }
    }
}

// ---------------------------------------------------------------------------
// Kernel 0b: shifted-window gather of x + bf16 hi/lo split, done ONCE.
// dst row m (window-token order), 192 cols. One float4 per thread.
// ---------------------------------------------------------------------------
__global__ __launch_bounds__(256) void prep_x(const float* __restrict__ x)
{
    int idx = blockIdx.x * 256 + threadIdx.x;      // < 3145728
    int m  = idx / 48;
    int c4 = idx - m * 48;
    int wbv = m >> 6, n = m & 63;
    int b  = wbv >> 8;
    int wh = (wbv >> 4) & 15;
    int ww = wbv & 15;
    int gh = (wh * 8 + (n >> 3) + 4) & 127;
    int gw = (ww * 8 + (n & 7) + 4) & 127;
    float4 v = *(const float4*)(x + ((size_t)((b * 128 + gh) * 128 + gw)) * CD
                                + c4 * 4);
    __nv_bfloat162 h01 = __float22bfloat162_rn(make_float2(v.x, v.y));
    __nv_bfloat162 h23 = __float22bfloat162_rn(make_float2(v.z, v.w));
    float2 f01 = __bfloat1622float2(h01);
    float2 f23 = __bfloat1622float2(h23);
    __nv_bfloat162 l01 = __float22bfloat162_rn(make_float2(v.x - f01.x, v.y - f01.y));
    __nv_bfloat162 l23 = __float22bfloat162_rn(make_float2(v.z - f23.x, v.w - f23.y));
    uint2 hh, ll;
    hh.x = *(uint32_t*)&h01; hh.y = *(uint32_t*)&h23;
    ll.x = *(uint32_t*)&l01; ll.y = *(uint32_t*)&l23;
    *(uint2*)(g_xh + (size_t)m * CD + c4 * 4) = hh;
    *(uint2*)(g_xl + (size_t)m * CD + c4 * 4) = ll;
}

// ---------------------------------------------------------------------------
// bf16x3 mma.sync GEMM; A pre-split in gmem (g_xh/g_xl or g_avh/g_avl).
// Block tile 128(M) x 64(N), K=192 in 3 chunks of 64. 8 warps, 32x32/warp.
// ---------------------------------------------------------------------------
#define OFF_AH 0
#define OFF_AL 18432
#define OFF_BH 36864
#define OFF_BL 62464
#define MM_SMEM 88064

template<bool QKV>
__global__ __launch_bounds__(256, 2) void mma_gemm(
    const float* __restrict__ bias,
    float* __restrict__ outp)            // used only in PROJ mode
{
    extern __shared__ char sm[];
    float* stage = (float*)sm;

    const __nv_bfloat16* ah = QKV ? g_xh : g_avh;
    const __nv_bfloat16* al = QKV ? g_xl : g_avl;

    const int t    = threadIdx.x;
    const int w    = t >> 5;
    const int lane = t & 31;
    const int bm   = blockIdx.x;
    const int bn   = blockIdx.y;
    const int wm   = w >> 1;
    const int wn   = w & 1;
    const int g    = lane >> 2;
    const int tg   = lane & 3;

    // ---- load B tile (64 n-rows, full K=192) hi+lo, once ----
    {
        const uint4* srch = (const uint4*)(QKV ? g_wt_hi : g_pt_hi);
        const uint4* srcl = (const uint4*)(QKV ? g_wt_lo : g_pt_lo);
        #pragma unroll
        for (int i = 0; i < 6; i++) {
            int idx = t + 256 * i;               // < 1536
            int row = idx / 24, c16 = idx - row * 24;
            uint32_t dst = (uint32_t)(row * 400 + c16 * 16);
            int src = (bn * 64 + row) * 24 + c16;
            *(uint4*)(sm + OFF_BH + dst) = srch[src];
            *(uint4*)(sm + OFF_BL + dst) = srcl[src];
        }
    }

    const int arow_l = t >> 1;
    const int seg    = t & 1;
    const size_t abase = (size_t)(bm * 128 + arow_l) * CD + seg * 32;
    const uint32_t a_sts = (uint32_t)(arow_l * 144 + seg * 64);

    float acc[2][4][4] = {};

    for (int c = 0; c < 3; c++) {
        const int k0 = c * 64;
        const uint32_t bko = (uint32_t)(c * 128);
        __syncthreads();
        // ---- A chunk: straight bf16 copy (4+4 uint4 per thread) ----
        {
            const uint4* sh = (const uint4*)(ah + abase + k0);
            const uint4* sl = (const uint4*)(al + abase + k0);
            uint4* dh = (uint4*)(sm + OFF_AH + a_sts);
            uint4* dl = (uint4*)(sm + OFF_AL + a_sts);
            #pragma unroll
            for (int q = 0; q < 4; q++) { dh[q] = sh[q]; dl[q] = sl[q]; }
        }
        __syncthreads();

        // ---- compute: 4 k-steps of 16, fragments via direct LDS ----
        #pragma unroll
        for (int ks = 0; ks < 4; ks++) {
            const uint32_t kb = (uint32_t)(ks * 32 + tg * 4);

            uint32_t Ah[2][4], Al[2][4];
            #pragma unroll
            for (int i = 0; i < 2; i++) {
                const uint32_t ab = (uint32_t)((wm * 32 + i * 16 + g) * 144) + kb;
                Ah[i][0] = *(const uint32_t*)(sm + OFF_AH + ab);
                Ah[i][1] = *(const uint32_t*)(sm + OFF_AH + ab + 8 * 144);
                Ah[i][2] = *(const uint32_t*)(sm + OFF_AH + ab + 16);
                Ah[i][3] = *(const uint32_t*)(sm + OFF_AH + ab + 8 * 144 + 16);
                Al[i][0] = *(const uint32_t*)(sm + OFF_AL + ab);
                Al[i][1] = *(const uint32_t*)(sm + OFF_AL + ab + 8 * 144);
                Al[i][2] = *(const uint32_t*)(sm + OFF_AL + ab + 16);
                Al[i][3] = *(const uint32_t*)(sm + OFF_AL + ab + 8 * 144 + 16);
            }
            uint32_t Bh[4][2], Bl[4][2];
            #pragma unroll
            for (int j = 0; j < 4; j++) {
                const uint32_t bb =
                    (uint32_t)((wn * 32 + j * 8 + g) * 400) + bko + kb;
                Bh[j][0] = *(const uint32_t*)(sm + OFF_BH + bb);
                Bh[j][1] = *(const uint32_t*)(sm + OFF_BH + bb + 16);
                Bl[j][0] = *(const uint32_t*)(sm + OFF_BL + bb);
                Bl[j][1] = *(const uint32_t*)(sm + OFF_BL + bb + 16);
            }
            #pragma unroll
            for (int i = 0; i < 2; i++)
                #pragma unroll
                for (int j = 0; j < 4; j++) {
                    mma_bf16(acc[i][j], Ah[i], Bh[j]);
                    mma_bf16(acc[i][j], Ah[i], Bl[j]);
                    mma_bf16(acc[i][j], Al[i], Bh[j]);
                }
        }
    }
    __syncthreads();

    // ---- stage C to smem (stride 68 floats) ----
    #pragma unroll
    for (int i = 0; i < 2; i++) {
        int row0 = wm * 32 + i * 16 + g;
        #pragma unroll
        for (int j = 0; j < 4; j++) {
            int col = wn * 32 + j * 8 + 2 * tg;
            *(float2*)&stage[row0 * 68 + col] =
                make_float2(acc[i][j][0], acc[i][j][1]);
            *(float2*)&stage[(row0 + 8) * 68 + col] =
                make_float2(acc[i][j][2], acc[i][j][3]);
        }
    }
    __syncthreads();

    // ---- coalesced store with bias (+ scatter for PROJ) ----
    const int s = t & 15;
    float4 b4 = *(const float4*)(bias + bn * 64 + s * 4);
    #pragma unroll
    for (int it = 0; it < 8; it++) {
        int row = (t >> 4) + 16 * it;
        float4 v = *(float4*)&stage[row * 68 + s * 4];
        v.x += b4.x; v.y += b4.y; v.z += b4.z; v.w += b4.w;
        if (QKV) {
            *(float4*)(g_qkv + (size_t)(bm * 128 + row) * C3 + bn * 64 + s * 4) = v;
        } else {
            int m = bm * 128 + row;
            int wbv = m >> 6, n = m & 63;
            int b  = wbv >> 8;
            int wh = (wbv >> 4) & 15;
            int ww = wbv & 15;
            int gh = (wh * 8 + (n >> 3) + 4) & 127;
            int gw = (ww * 8 + (n & 7) + 4) & 127;
            *(float4*)(outp + ((size_t)((b * 128 + gh) * 128 + gw)) * CD
                       + bn * 64 + s * 4) = v;
        }
    }
}

// ---------------------------------------------------------------------------
// Kernel 2: LePE + gated attention + softmax + attn@V.
// 384 thr, 2 blocks/SM target. smem: v'(12288) + kT(6*32*66=12672) +
// lepe(1728+192) = 26880 floats = 107520 B. q read straight from gmem.
// Output written as bf16 hi/lo for the proj GEMM.
// ---------------------------------------------------------------------------
#define KT_STRIDE 66
#define KT_HEAD   (32 * KT_STRIDE)   // 2112
#define ATTN_SMEM (26880 * 4)

__global__ __launch_bounds__(384, 2) void attn3(
    const float* __restrict__ prev,
    const float* __restrict__ lepe_w,
    const float* __restrict__ lepe_b,
    float* __restrict__ out)
{
    extern __shared__ float smf[];
    float* sv2 = smf;            // v + lepe(v), [n][192]
    float* skT = smf + 12288;    // raw v, then k^T [h][d][66]
    float* swb = smf + 24960;    // 1728
    float* slb = smf + 26688;    // 192

    const int t  = threadIdx.x;
    const int wb = blockIdx.x;
    const float* qb = g_qkv + (size_t)wb * NTOK * C3;

    // ---- stage raw v (flat) + lepe params ----
    for (int idx = t; idx < NTOK * CD; idx += 384) {
        int n = idx / CD, c = idx - n * CD;
        skT[idx] = qb[n * C3 + 2 * CD + c];
    }
    for (int idx = t; idx < 9 * CD; idx += 384) swb[idx] = lepe_w[idx];
    if (t < CD) slb[t] = lepe_b[t];
    __syncthreads();

    // ---- LePE depthwise 3x3 within the 8x8 window ----
    for (int idx = t; idx < NTOK * CD; idx += 384) {
        int n = idx / CD, c = idx - n * CD;
        int i = n >> 3, j = n & 7;
        float a = slb[c];
        #pragma unroll
        for (int kh = 0; kh < 3; kh++) {
            int ii = i + kh - 1;
            if ((unsigned)ii >= 8u) continue;
            #pragma unroll
            for (int kw = 0; kw < 3; kw++) {
                int jj = j + kw - 1;
                if ((unsigned)jj < 8u)
                    a = fmaf(skT[(ii * 8 + jj) * CD + c],
                             swb[(kh * 3 + kw) * CD + c], a);
            }
        }
        sv2[idx] = skT[idx] + a;
    }
    __syncthreads();

    // ---- k^T into skT ----
    for (int idx = t; idx < NTOK * CD; idx += 384) {
        int n = idx / CD, c = idx - n * CD;
        int h = c >> 5, d = c & 31;
        skT[h * KT_HEAD + d * KT_STRIDE + n] = qb[n * C3 + CD + c];
    }
    __syncthreads();

    const int w    = t >> 5;
    const int lane = t & 31;
    const int h    = w >> 1;
    const int r    = ((w & 1) << 5) | lane;
    const float* kh = skT + h * KT_HEAD;
    const float* qrow = qb + (size_t)r * C3 + h * 32;

    // ---- scores: q from gmem (float4 at a time), k^T broadcast from smem ----
    float2 sc[32];
    #pragma unroll
    for (int i = 0; i < 32; i++) sc[i] = make_float2(0.f, 0.f);
    #pragma unroll
    for (int db = 0; db < 8; db++) {
        float4 q4 = *(const float4*)(qrow + db * 4);
        q4.x *= ATTN_SCALE; q4.y *= ATTN_SCALE;
        q4.z *= ATTN_SCALE; q4.w *= ATTN_SCALE;
        const float qv[4] = {q4.x, q4.y, q4.z, q4.w};
        #pragma unroll
        for (int dd = 0; dd < 4; dd++) {
            unsigned long long qs = pack2(qv[dd], qv[dd]);
            const unsigned long long* kd =
                (const unsigned long long*)(kh + (db * 4 + dd) * KT_STRIDE);
            #pragma unroll
            for (int jp = 0; jp < 32; jp++)
                ffma2(*(unsigned long long*)&sc[jp], qs, kd[jp]);
        }
    }

    float* p = (float*)sc;
    const float* pr = prev + (((size_t)(wb * 6 + h)) * 64 + r) * 64;
    #pragma unroll
    for (int i = 0; i < 16; i++) {
        float4 pv = ((const float4*)pr)[i];
        p[4*i+0] *= pv.x; p[4*i+1] *= pv.y; p[4*i+2] *= pv.z; p[4*i+3] *= pv.w;
    }

    // ---- softmax (register-local) ----
    float mx = p[0];
    #pragma unroll
    for (int i = 1; i < 64; i++) mx = fmaxf(mx, p[i]);
    float s = 0.f;
    #pragma unroll
    for (int i = 0; i < 64; i++) { p[i] = __expf(p[i] - mx); s += p[i]; }
    float inv = 1.0f / s;

    float* ao = out + OUT_ELEMS + (((size_t)(wb * 6 + h)) * 64 + r) * 64;
    #pragma unroll
    for (int i = 0; i < 16; i++) {
        float4 o;
        o.x = p[4*i+0] * inv; o.y = p[4*i+1] * inv;
        o.z = p[4*i+2] * inv; o.w = p[4*i+3] * inv;
        p[4*i+0] = o.x; p[4*i+1] = o.y; p[4*i+2] = o.z; p[4*i+3] = o.w;
        ((float4*)ao)[i] = o;
    }

    // ---- attn @ v', two 16-dim halves; write bf16 hi/lo ----
    const size_t obase = ((size_t)(wb * 64 + r)) * CD + h * 32;
    #pragma unroll
    for (int half = 0; half < 2; half++) {
        float2 o2[8];
        #pragma unroll
        for (int i = 0; i < 8; i++) o2[i] = make_float2(0.f, 0.f);
        for (int j = 0; j < 64; j++) {
            unsigned long long ps = pack2(p[j], p[j]);
            const unsigned long long* vr =
                (const unsigned long long*)(sv2 + j * CD + h * 32 + half * 16);
            #pragma unroll
            for (int dp = 0; dp < 8; dp++)
                ffma2(*(unsigned long long*)&o2[dp], ps, vr[dp]);
        }
        uint32_t hv[8], lv[8];
        #pragma unroll
        for (int i = 0; i < 8; i++) {
            __nv_bfloat162 hb = __float22bfloat162_rn(o2[i]);
            float2 hf = __bfloat1622float2(hb);
            __nv_bfloat162 lb = __float22bfloat162_rn(
                make_float2(o2[i].x - hf.x, o2[i].y - hf.y));
            hv[i] = *(uint32_t*)&hb;
            lv[i] = *(uint32_t*)&lb;
        }
        uint4* dh = (uint4*)(g_avh + obase + half * 16);
        uint4* dl = (uint4*)(g_avl + obase + half * 16);
        dh[0] = make_uint4(hv[0], hv[1], hv[2], hv[3]);
        dh[1] = make_uint4(hv[4], hv[5], hv[6], hv[7]);
        dl[0] = make_uint4(lv[0], lv[1], lv[2], lv[3]);
        dl[1] = make_uint4(lv[4], lv[5], lv[6], lv[7]);
    }
}

// ---------------------------------------------------------------------------
extern "C" void kernel_launch(void* const* d_in, const int* in_sizes, int n_in,
                              void* d_out, int out_size)
{
    const float* x      = (const float*)d_in[0];
    const float* prev   = (const float*)d_in[1];
    const float* qkv_w  = (const float*)d_in[2];
    const float* qkv_b  = (const float*)d_in[3];
    const float* proj_w = (const float*)d_in[4];
    const float* proj_b = (const float*)d_in[5];
    const float* lepe_w = (const float*)d_in[6];
    const float* lepe_b = (const float*)d_in[7];
    float* out = (float*)d_out;

    cudaFuncSetAttribute(attn3,
                         cudaFuncAttributeMaxDynamicSharedMemorySize, ATTN_SMEM);
    cudaFuncSetAttribute(mma_gemm<true>,
                         cudaFuncAttributeMaxDynamicSharedMemorySize, MM_SMEM);
    cudaFuncSetAttribute(mma_gemm<false>,
                         cudaFuncAttributeMaxDynamicSharedMemorySize, MM_SMEM);

    prep_w<<<576, 256>>>(qkv_w, proj_w);
    prep_x<<<12288, 256>>>(x);
    mma_gemm<true><<<dim3(512, 9), 256, MM_SMEM>>>(qkv_b, nullptr);
    attn3<<<NWIN, 384, ATTN_SMEM>>>(prev, lepe_w, lepe_b, out);
    mma_gemm<false><<<dim3(512, 3), 256, MM_SMEM>>>(proj_b, out);
}

// round 9
// speedup vs baseline: 1.9320x; 1.2918x over previous
#include <cuda_runtime.h>
#include <cuda_bf16.h>
#include <math.h>
#include <stdint.h>

#define NWIN 1024
#define NTOK 64
#define CD   192
#define C3   576
#define NROW 65536
#define OUT_ELEMS 12582912
#define ATTN_SCALE 0.17677669529663687f

// ---------------- device scratch ----------------
static __device__ __align__(16) float g_qkv[NWIN * NTOK * C3];
static __device__ __align__(16) __nv_bfloat16 g_xh[NROW * CD];
static __device__ __align__(16) __nv_bfloat16 g_xl[NROW * CD];
static __device__ __align__(16) __nv_bfloat16 g_avh[NROW * CD];
static __device__ __align__(16) __nv_bfloat16 g_avl[NROW * CD];
static __device__ __align__(16) __nv_bfloat16 g_wt_hi[C3 * CD];
static __device__ __align__(16) __nv_bfloat16 g_wt_lo[C3 * CD];
static __device__ __align__(16) __nv_bfloat16 g_pt_hi[CD * CD];
static __device__ __align__(16) __nv_bfloat16 g_pt_lo[CD * CD];

// ---------------- PTX helpers ----------------
__device__ __forceinline__ void ffma2(unsigned long long& d,
                                      unsigned long long a,
                                      unsigned long long b) {
    asm("fma.rn.f32x2 %0, %1, %2, %0;" : "+l"(d) : "l"(a), "l"(b));
}
__device__ __forceinline__ unsigned long long pack2(float lo, float hi) {
    unsigned long long r;
    asm("mov.b64 %0, {%1, %2};" : "=l"(r) : "f"(lo), "f"(hi));
    return r;
}
__device__ __forceinline__ uint32_t smem_u32(const void* p) {
    uint32_t a;
    asm("{ .reg .u64 t; cvta.to.shared.u64 t, %1; cvt.u32.u64 %0, t; }"
        : "=r"(a) : "l"(p));
    return a;
}
__device__ __forceinline__ void mma_bf16(float* c, const uint32_t* a,
                                         const uint32_t* b) {
    asm volatile(
        "mma.sync.aligned.m16n8k16.row.col.f32.bf16.bf16.f32 "
        "{%0,%1,%2,%3}, {%4,%5,%6,%7}, {%8,%9}, {%0,%1,%2,%3};"
        : "+f"(c[0]), "+f"(c[1]), "+f"(c[2]), "+f"(c[3])
        : "r"(a[0]), "r"(a[1]), "r"(a[2]), "r"(a[3]), "r"(b[0]), "r"(b[1]));
}
__device__ __forceinline__ void cp_async16(uint32_t dst, const void* src) {
    asm volatile("cp.async.cg.shared.global [%0], [%1], 16;\n"
                 :: "r"(dst), "l"(src));
}
#define CP_COMMIT() asm volatile("cp.async.commit_group;\n" ::: "memory")
#define CP_WAIT(n)  asm volatile("cp.async.wait_group %0;\n" :: "n"(n) : "memory")

// ---------------------------------------------------------------------------
// Kernel 0a: weight pre-transpose + bf16 hi/lo split.
// ---------------------------------------------------------------------------
__global__ __launch_bounds__(256) void prep_w(const float* __restrict__ qkv_w,
                                              const float* __restrict__ proj_w)
{
    int idx = blockIdx.x * 256 + threadIdx.x;
    if (idx < C3 * CD) {
        int n = idx / CD, k = idx - n * CD;
        float v = qkv_w[k * C3 + n];
        __nv_bfloat16 h = __float2bfloat16_rn(v);
        g_wt_hi[idx] = h;
        g_wt_lo[idx] = __float2bfloat16_rn(v - __bfloat162float(h));
    } else {
        int j = idx - C3 * CD;
        if (j < CD * CD) {
            int n = j / CD, k = j - n * CD;
            float v = proj_w[k * CD + n];
            __nv_bfloat16 h = __float2bfloat16_rn(v);
            g_pt_hi[j] = h;
            g_pt_lo[j] = __float2bfloat16_rn(v - __bfloat162float(h));
        }
    }
}

// ---------------------------------------------------------------------------
// Kernel 0b: shifted-window gather of x + bf16 hi/lo split.
// ---------------------------------------------------------------------------
__global__ __launch_bounds__(256) void prep_x(const float* __restrict__ x)
{
    int idx = blockIdx.x * 256 + threadIdx.x;
    int m  = idx / 48;
    int c4 = idx - m * 48;
    int wbv = m >> 6, n = m & 63;
    int b  = wbv >> 8;
    int wh = (wbv >> 4) & 15;
    int ww = wbv & 15;
    int gh = (wh * 8 + (n >> 3) + 4) & 127;
    int gw = (ww * 8 + (n & 7) + 4) & 127;
    float4 v = *(const float4*)(x + ((size_t)((b * 128 + gh) * 128 + gw)) * CD
                                + c4 * 4);
    __nv_bfloat162 h01 = __float22bfloat162_rn(make_float2(v.x, v.y));
    __nv_bfloat162 h23 = __float22bfloat162_rn(make_float2(v.z, v.w));
    float2 f01 = __bfloat1622float2(h01);
    float2 f23 = __bfloat1622float2(h23);
    __nv_bfloat162 l01 = __float22bfloat162_rn(make_float2(v.x - f01.x, v.y - f01.y));
    __nv_bfloat162 l23 = __float22bfloat162_rn(make_float2(v.z - f23.x, v.w - f23.y));
    uint2 hh, ll;
    hh.x = *(uint32_t*)&h01; hh.y = *(uint32_t*)&h23;
    ll.x = *(uint32_t*)&l01; ll.y = *(uint32_t*)&l23;
    *(uint2*)(g_xh + (size_t)m * CD + c4 * 4) = hh;
    *(uint2*)(g_xl + (size_t)m * CD + c4 * 4) = ll;
}

// ---------------------------------------------------------------------------
// bf16x3 mma.sync GEMM with cp.async double-buffered A and B chunks.
// Block tile 128(M) x 64(N), K=192 in 3 chunks of 64. 8 warps, 32x32/warp.
// smem (bytes): Abuf0 hi 0, lo 16384 | Abuf1 hi 32768, lo 49152 |
//               Bbuf0 hi 65536, lo 73728 | Bbuf1 hi 81920, lo 90112. = 98304.
// XOR swizzle: 16B slot s of row r stored at slot (s ^ (r&7)).
// ---------------------------------------------------------------------------
#define MM_SMEM 98304

template<bool QKV>
__global__ __launch_bounds__(256, 2) void mma_gemm(
    const float* __restrict__ bias,
    float* __restrict__ outp)
{
    extern __shared__ char sm[];
    const uint32_t smb = smem_u32(sm);
    float* stage = (float*)sm;

    const __nv_bfloat16* ah = QKV ? g_xh : g_avh;
    const __nv_bfloat16* al = QKV ? g_xl : g_avl;
    const __nv_bfloat16* bh = QKV ? g_wt_hi : g_pt_hi;
    const __nv_bfloat16* bl = QKV ? g_wt_lo : g_pt_lo;

    const int t    = threadIdx.x;
    const int w    = t >> 5;
    const int lane = t & 31;
    const int bm   = blockIdx.x;
    const int bn   = blockIdx.y;
    const int wm   = w >> 1;
    const int wn   = w & 1;
    const int g    = lane >> 2;
    const int tg   = lane & 3;

    // loader lambdas (per chunk c into buffer buf)
    auto prefetch = [&](int c, int buf) {
        const uint32_t aB = smb + (buf ? 32768u : 0u);
        const uint32_t bB = smb + 65536u + (buf ? 16384u : 0u);
        #pragma unroll
        for (int q = 0; q < 4; q++) {
            int idx = t + 256 * q;               // < 1024
            int row = idx >> 3, slot = idx & 7;
            uint32_t dst = aB + (uint32_t)(row * 128 + ((slot ^ (row & 7)) << 4));
            size_t src = (size_t)(bm * 128 + row) * CD + c * 64 + slot * 8;
            cp_async16(dst,          ah + src);
            cp_async16(dst + 16384u, al + src);
        }
        #pragma unroll
        for (int q = 0; q < 2; q++) {
            int idx = t + 256 * q;               // < 512
            int row = idx >> 3, slot = idx & 7;
            uint32_t dst = bB + (uint32_t)(row * 128 + ((slot ^ (row & 7)) << 4));
            size_t src = (size_t)(bn * 64 + row) * CD + c * 64 + slot * 8;
            cp_async16(dst,         bh + src);
            cp_async16(dst + 8192u, bl + src);
        }
    };

    float acc[2][4][4] = {};

    prefetch(0, 0); CP_COMMIT();
    prefetch(1, 1); CP_COMMIT();

    #pragma unroll
    for (int c = 0; c < 3; c++) {
        if (c < 2) CP_WAIT(1); else CP_WAIT(0);
        __syncthreads();

        const char* Ah_s = sm + ((c & 1) ? 32768 : 0);
        const char* Al_s = Ah_s + 16384;
        const char* Bh_s = sm + 65536 + ((c & 1) ? 16384 : 0);
        const char* Bl_s = Bh_s + 8192;

        #pragma unroll
        for (int ks = 0; ks < 4; ks++) {
            const uint32_t s0 = (uint32_t)((2 * ks) ^ g) << 4;
            const uint32_t s1 = (uint32_t)((2 * ks + 1) ^ g) << 4;
            const uint32_t tw = (uint32_t)(tg * 4);

            uint32_t Ah[2][4], Al[2][4];
            #pragma unroll
            for (int i = 0; i < 2; i++) {
                const uint32_t rb = (uint32_t)((wm * 32 + i * 16 + g) * 128);
                Ah[i][0] = *(const uint32_t*)(Ah_s + rb + s0 + tw);
                Ah[i][1] = *(const uint32_t*)(Ah_s + rb + 1024 + s0 + tw);
                Ah[i][2] = *(const uint32_t*)(Ah_s + rb + s1 + tw);
                Ah[i][3] = *(const uint32_t*)(Ah_s + rb + 1024 + s1 + tw);
                Al[i][0] = *(const uint32_t*)(Al_s + rb + s0 + tw);
                Al[i][1] = *(const uint32_t*)(Al_s + rb + 1024 + s0 + tw);
                Al[i][2] = *(const uint32_t*)(Al_s + rb + s1 + tw);
                Al[i][3] = *(const uint32_t*)(Al_s + rb + 1024 + s1 + tw);
            }
            uint32_t Bh[4][2], Bl[4][2];
            #pragma unroll
            for (int j = 0; j < 4; j++) {
                const uint32_t nb = (uint32_t)((wn * 32 + j * 8 + g) * 128);
                Bh[j][0] = *(const uint32_t*)(Bh_s + nb + s0 + tw);
                Bh[j][1] = *(const uint32_t*)(Bh_s + nb + s1 + tw);
                Bl[j][0] = *(const uint32_t*)(Bl_s + nb + s0 + tw);
                Bl[j][1] = *(const uint32_t*)(Bl_s + nb + s1 + tw);
            }
            #pragma unroll
            for (int i = 0; i < 2; i++)
                #pragma unroll
                for (int j = 0; j < 4; j++) {
                    mma_bf16(acc[i][j], Ah[i], Bh[j]);
                    mma_bf16(acc[i][j], Ah[i], Bl[j]);
                    mma_bf16(acc[i][j], Al[i], Bh[j]);
                }
        }
        __syncthreads();
        if (c + 2 < 3) { prefetch(c + 2, (c + 2) & 1); CP_COMMIT(); }
    }

    // ---- stage C to smem (stride 68 floats) ----
    #pragma unroll
    for (int i = 0; i < 2; i++) {
        int row0 = wm * 32 + i * 16 + g;
        #pragma unroll
        for (int j = 0; j < 4; j++) {
            int col = wn * 32 + j * 8 + 2 * tg;
            *(float2*)&stage[row0 * 68 + col] =
                make_float2(acc[i][j][0], acc[i][j][1]);
            *(float2*)&stage[(row0 + 8) * 68 + col] =
                make_float2(acc[i][j][2], acc[i][j][3]);
        }
    }
    __syncthreads();

    // ---- coalesced store with bias (+ scatter for PROJ) ----
    const int s = t & 15;
    float4 b4 = *(const float4*)(bias + bn * 64 + s * 4);
    #pragma unroll
    for (int it = 0; it < 8; it++) {
        int row = (t >> 4) + 16 * it;
        float4 v = *(float4*)&stage[row * 68 + s * 4];
        v.x += b4.x; v.y += b4.y; v.z += b4.z; v.w += b4.w;
        if (QKV) {
            *(float4*)(g_qkv + (size_t)(bm * 128 + row) * C3 + bn * 64 + s * 4) = v;
        } else {
            int m = bm * 128 + row;
            int wbv = m >> 6, n = m & 63;
            int b  = wbv >> 8;
            int wh = (wbv >> 4) & 15;
            int ww = wbv & 15;
            int gh = (wh * 8 + (n >> 3) + 4) & 127;
            int gw = (ww * 8 + (n & 7) + 4) & 127;
            *(float4*)(outp + ((size_t)((b * 128 + gh) * 128 + gw)) * CD
                       + bn * 64 + s * 4) = v;
        }
    }
}

// ---------------------------------------------------------------------------
// Kernel 2: LePE + gated attention + softmax + attn@V.
// Reordered: k^T + v loads front-loaded; LePE in-place via registers.
// ---------------------------------------------------------------------------
#define KT_STRIDE 66
#define KT_HEAD   (32 * KT_STRIDE)
#define ATTN_SMEM (26880 * 4)

__global__ __launch_bounds__(384, 2) void attn3(
    const float* __restrict__ prev,
    const float* __restrict__ lepe_w,
    const float* __restrict__ lepe_b,
    float* __restrict__ out)
{
    extern __shared__ float smf[];
    float* sv2 = smf;            // raw v, then v' in place, [n][192]
    float* skT = smf + 12288;    // k^T [h][d][66]
    float* swb = smf + 24960;    // 1728
    float* slb = smf + 26688;    // 192

    const int t  = threadIdx.x;
    const int wb = blockIdx.x;
    const float* qb = g_qkv + (size_t)wb * NTOK * C3;

    // ---- front-loaded gmem: k^T transpose-store + raw v + lepe params ----
    for (int idx = t; idx < NTOK * CD; idx += 384) {
        int n = idx / CD, c = idx - n * CD;
        int h = c >> 5, d = c & 31;
        skT[h * KT_HEAD + d * KT_STRIDE + n] = qb[n * C3 + CD + c];
        sv2[idx] = qb[n * C3 + 2 * CD + c];
    }
    for (int idx = t; idx < 9 * CD; idx += 384) swb[idx] = lepe_w[idx];
    if (t < CD) slb[t] = lepe_b[t];
    __syncthreads();

    // ---- LePE into registers (32 elems/thread), then write back in place ----
    float lep[32];
    #pragma unroll
    for (int q = 0; q < 32; q++) {
        int idx = t + 384 * q;
        int n = idx / CD, c = idx - n * CD;
        int i = n >> 3, j = n & 7;
        float a = slb[c];
        #pragma unroll
        for (int kh = 0; kh < 3; kh++) {
            int ii = i + kh - 1;
            if ((unsigned)ii >= 8u) continue;
            #pragma unroll
            for (int kw = 0; kw < 3; kw++) {
                int jj = j + kw - 1;
                if ((unsigned)jj < 8u)
                    a = fmaf(sv2[(ii * 8 + jj) * CD + c],
                             swb[(kh * 3 + kw) * CD + c], a);
            }
        }
        lep[q] = sv2[idx] + a;
    }
    __syncthreads();
    #pragma unroll
    for (int q = 0; q < 32; q++) sv2[t + 384 * q] = lep[q];
    __syncthreads();

    const int w    = t >> 5;
    const int lane = t & 31;
    const int h    = w >> 1;
    const int r    = ((w & 1) << 5) | lane;
    const float* kh = skT + h * KT_HEAD;
    const float* qrow = qb + (size_t)r * C3 + h * 32;

    // ---- scores ----
    float2 sc[32];
    #pragma unroll
    for (int i = 0; i < 32; i++) sc[i] = make_float2(0.f, 0.f);
    #pragma unroll
    for (int db = 0; db < 8; db++) {
        float4 q4 = *(const float4*)(qrow + db * 4);
        q4.x *= ATTN_SCALE; q4.y *= ATTN_SCALE;
        q4.z *= ATTN_SCALE; q4.w *= ATTN_SCALE;
        const float qv[4] = {q4.x, q4.y, q4.z, q4.w};
        #pragma unroll
        for (int dd = 0; dd < 4; dd++) {
            unsigned long long qs = pack2(qv[dd], qv[dd]);
            const unsigned long long* kd =
                (const unsigned long long*)(kh + (db * 4 + dd) * KT_STRIDE);
            #pragma unroll
            for (int jp = 0; jp < 32; jp++)
                ffma2(*(unsigned long long*)&sc[jp], qs, kd[jp]);
        }
    }

    float* p = (float*)sc;
    const float* pr = prev + (((size_t)(wb * 6 + h)) * 64 + r) * 64;
    #pragma unroll
    for (int i = 0; i < 16; i++) {
        float4 pv = ((const float4*)pr)[i];
        p[4*i+0] *= pv.x; p[4*i+1] *= pv.y; p[4*i+2] *= pv.z; p[4*i+3] *= pv.w;
    }

    // ---- softmax ----
    float mx = p[0];
    #pragma unroll
    for (int i = 1; i < 64; i++) mx = fmaxf(mx, p[i]);
    float s = 0.f;
    #pragma unroll
    for (int i = 0; i < 64; i++) { p[i] = __expf(p[i] - mx); s += p[i]; }
    float inv = 1.0f / s;

    float* ao = out + OUT_ELEMS + (((size_t)(wb * 6 + h)) * 64 + r) * 64;
    #pragma unroll
    for (int i = 0; i < 16; i++) {
        float4 o;
        o.x = p[4*i+0] * inv; o.y = p[4*i+1] * inv;
        o.z = p[4*i+2] * inv; o.w = p[4*i+3] * inv;
        p[4*i+0] = o.x; p[4*i+1] = o.y; p[4*i+2] = o.z; p[4*i+3] = o.w;
        ((float4*)ao)[i] = o;
    }

    // ---- attn @ v', two 16-dim halves; write bf16 hi/lo ----
    const size_t obase = ((size_t)(wb * 64 + r)) * CD + h * 32;
    #pragma unroll
    for (int half = 0; half < 2; half++) {
        float2 o2[8];
        #pragma unroll
        for (int i = 0; i < 8; i++) o2[i] = make_float2(0.f, 0.f);
        for (int j = 0; j < 64; j++) {
            unsigned long long ps = pack2(p[j], p[j]);
            const unsigned long long* vr =
                (const unsigned long long*)(sv2 + j * CD + h * 32 + half * 16);
            #pragma unroll
            for (int dp = 0; dp < 8; dp++)
                ffma2(*(unsigned long long*)&o2[dp], ps, vr[dp]);
        }
        uint32_t hv[8], lv[8];
        #pragma unroll
        for (int i = 0; i < 8; i++) {
            __nv_bfloat162 hb = __float22bfloat162_rn(o2[i]);
            float2 hf = __bfloat1622float2(hb);
            __nv_bfloat162 lb = __float22bfloat162_rn(
                make_float2(o2[i].x - hf.x, o2[i].y - hf.y));
            hv[i] = *(uint32_t*)&hb;
            lv[i] = *(uint32_t*)&lb;
        }
        uint4* dh = (uint4*)(g_avh + obase + half * 16);
        uint4* dl = (uint4*)(g_avl + obase + half * 16);
        dh[0] = make_uint4(hv[0], hv[1], hv[2], hv[3]);
        dh[1] = make_uint4(hv[4], hv[5], hv[6], hv[7]);
        dl[0] = make_uint4(lv[0], lv[1], lv[2], lv[3]);
        dl[1] = make_uint4(lv[4], lv[5], lv[6], lv[7]);
    }
}

// ---------------------------------------------------------------------------
extern "C" void kernel_launch(void* const* d_in, const int* in_sizes, int n_in,
                              void* d_out, int out_size)
{
    const float* x      = (const float*)d_in[0];
    const float* prev   = (const float*)d_in[1];
    const float* qkv_w  = (const float*)d_in[2];
    const float* qkv_b  = (const float*)d_in[3];
    const float* proj_w = (const float*)d_in[4];
    const float* proj_b = (const float*)d_in[5];
    const float* lepe_w = (const float*)d_in[6];
    const float* lepe_b = (const float*)d_in[7];
    float* out = (float*)d_out;

    cudaFuncSetAttribute(attn3,
                         cudaFuncAttributeMaxDynamicSharedMemorySize, ATTN_SMEM);
    cudaFuncSetAttribute(mma_gemm<true>,
                         cudaFuncAttributeMaxDynamicSharedMemorySize, MM_SMEM);
    cudaFuncSetAttribute(mma_gemm<false>,
                         cudaFuncAttributeMaxDynamicSharedMemorySize, MM_SMEM);

    prep_w<<<576, 256>>>(qkv_w, proj_w);
    prep_x<<<12288, 256>>>(x);
    mma_gemm<true><<<dim3(512, 9), 256, MM_SMEM>>>(qkv_b, nullptr);
    attn3<<<NWIN, 384, ATTN_SMEM>>>(prev, lepe_w, lepe_b, out);
    mma_gemm<false><<<dim3(512, 3), 256, MM_SMEM>>>(proj_b, out);
}

// round 10
// speedup vs baseline: 2.8317x; 1.4657x over previous
#include <cuda_runtime.h>
#include <cuda_bf16.h>
#include <math.h>
#include <stdint.h>

#define NWIN 1024
#define NTOK 64
#define CD   192
#define C3   576
#define NROW 65536
#define OUT_ELEMS 12582912
#define ATTN_SCALE 0.17677669529663687f

// ---------------- device scratch ----------------
static __device__ __align__(16) __nv_bfloat16 g_qbf[NROW * CD];  // q, bias+scaled
static __device__ __align__(16) __nv_bfloat16 g_kbf[NROW * CD];  // k, bias
static __device__ __align__(16) float         g_vf [NROW * CD];  // v fp32
static __device__ __align__(16) __nv_bfloat16 g_xh[NROW * CD];
static __device__ __align__(16) __nv_bfloat16 g_xl[NROW * CD];
static __device__ __align__(16) __nv_bfloat16 g_avh[NROW * CD];
static __device__ __align__(16) __nv_bfloat16 g_avl[NROW * CD];
static __device__ __align__(16) __nv_bfloat16 g_wt_hi[C3 * CD];
static __device__ __align__(16) __nv_bfloat16 g_wt_lo[C3 * CD];
static __device__ __align__(16) __nv_bfloat16 g_pt_hi[CD * CD];
static __device__ __align__(16) __nv_bfloat16 g_pt_lo[CD * CD];

// ---------------- PTX helpers ----------------
__device__ __forceinline__ uint32_t smem_u32(const void* p) {
    uint32_t a;
    asm("{ .reg .u64 t; cvta.to.shared.u64 t, %1; cvt.u32.u64 %0, t; }"
        : "=r"(a) : "l"(p));
    return a;
}
__device__ __forceinline__ void mma_bf16(float* c, const uint32_t* a,
                                         const uint32_t* b) {
    asm volatile(
        "mma.sync.aligned.m16n8k16.row.col.f32.bf16.bf16.f32 "
        "{%0,%1,%2,%3}, {%4,%5,%6,%7}, {%8,%9}, {%0,%1,%2,%3};"
        : "+f"(c[0]), "+f"(c[1]), "+f"(c[2]), "+f"(c[3])
        : "r"(a[0]), "r"(a[1]), "r"(a[2]), "r"(a[3]), "r"(b[0]), "r"(b[1]));
}
__device__ __forceinline__ void cp_async16(uint32_t dst, const void* src) {
    asm volatile("cp.async.cg.shared.global [%0], [%1], 16;\n"
                 :: "r"(dst), "l"(src));
}
#define CP_COMMIT() asm volatile("cp.async.commit_group;\n" ::: "memory")
#define CP_WAIT(n)  asm volatile("cp.async.wait_group %0;\n" :: "n"(n) : "memory")

__device__ __forceinline__ uint32_t bf2_of(float x, float y) {
    __nv_bfloat162 h = __float22bfloat162_rn(make_float2(x, y));
    return *(uint32_t*)&h;
}
__device__ __forceinline__ uint32_t bf2_lo_of(float x, float y, uint32_t hi) {
    __nv_bfloat162 hb = *(__nv_bfloat162*)&hi;
    float2 hf = __bfloat1622float2(hb);
    __nv_bfloat162 l = __float22bfloat162_rn(make_float2(x - hf.x, y - hf.y));
    return *(uint32_t*)&l;
}

// ---------------------------------------------------------------------------
// Kernel 0a: weight pre-transpose + bf16 hi/lo split.
// ---------------------------------------------------------------------------
__global__ __launch_bounds__(256) void prep_w(const float* __restrict__ qkv_w,
                                              const float* __restrict__ proj_w)
{
    int idx = blockIdx.x * 256 + threadIdx.x;
    if (idx < C3 * CD) {
        int n = idx / CD, k = idx - n * CD;
        float v = qkv_w[k * C3 + n];
        __nv_bfloat16 h = __float2bfloat16_rn(v);
        g_wt_hi[idx] = h;
        g_wt_lo[idx] = __float2bfloat16_rn(v - __bfloat162float(h));
    } else {
        int j = idx - C3 * CD;
        if (j < CD * CD) {
            int n = j / CD, k = j - n * CD;
            float v = proj_w[k * CD + n];
            __nv_bfloat16 h = __float2bfloat16_rn(v);
            g_pt_hi[j] = h;
            g_pt_lo[j] = __float2bfloat16_rn(v - __bfloat162float(h));
        }
    }
}

// ---------------------------------------------------------------------------
// Kernel 0b: shifted-window gather of x + bf16 hi/lo split.
// ---------------------------------------------------------------------------
__global__ __launch_bounds__(256) void prep_x(const float* __restrict__ x)
{
    int idx = blockIdx.x * 256 + threadIdx.x;
    int m  = idx / 48;
    int c4 = idx - m * 48;
    int wbv = m >> 6, n = m & 63;
    int b  = wbv >> 8;
    int wh = (wbv >> 4) & 15;
    int ww = wbv & 15;
    int gh = (wh * 8 + (n >> 3) + 4) & 127;
    int gw = (ww * 8 + (n & 7) + 4) & 127;
    float4 v = *(const float4*)(x + ((size_t)((b * 128 + gh) * 128 + gw)) * CD
                                + c4 * 4);
    __nv_bfloat162 h01 = __float22bfloat162_rn(make_float2(v.x, v.y));
    __nv_bfloat162 h23 = __float22bfloat162_rn(make_float2(v.z, v.w));
    float2 f01 = __bfloat1622float2(h01);
    float2 f23 = __bfloat1622float2(h23);
    __nv_bfloat162 l01 = __float22bfloat162_rn(make_float2(v.x - f01.x, v.y - f01.y));
    __nv_bfloat162 l23 = __float22bfloat162_rn(make_float2(v.z - f23.x, v.w - f23.y));
    uint2 hh, ll;
    hh.x = *(uint32_t*)&h01; hh.y = *(uint32_t*)&h23;
    ll.x = *(uint32_t*)&l01; ll.y = *(uint32_t*)&l23;
    *(uint2*)(g_xh + (size_t)m * CD + c4 * 4) = hh;
    *(uint2*)(g_xl + (size_t)m * CD + c4 * 4) = ll;
}

// ---------------------------------------------------------------------------
// bf16x3 mma.sync GEMM with cp.async double buffering (passing round-9 core).
// QKV epilogue now emits q (scaled, bf16), k (bf16), v (fp32) to split buffers.
// ---------------------------------------------------------------------------
#define MM_SMEM 98304

template<bool QKV>
__global__ __launch_bounds__(256, 2) void mma_gemm(
    const float* __restrict__ bias,
    float* __restrict__ outp)
{
    extern __shared__ char sm[];
    const uint32_t smb = smem_u32(sm);
    float* stage = (float*)sm;

    const __nv_bfloat16* ah = QKV ? g_xh : g_avh;
    const __nv_bfloat16* al = QKV ? g_xl : g_avl;
    const __nv_bfloat16* bh = QKV ? g_wt_hi : g_pt_hi;
    const __nv_bfloat16* bl = QKV ? g_wt_lo : g_pt_lo;

    const int t    = threadIdx.x;
    const int w    = t >> 5;
    const int lane = t & 31;
    const int bm   = blockIdx.x;
    const int bn   = blockIdx.y;
    const int wm   = w >> 1;
    const int wn   = w & 1;
    const int g    = lane >> 2;
    const int tg   = lane & 3;

    auto prefetch = [&](int c, int buf) {
        const uint32_t aB = smb + (buf ? 32768u : 0u);
        const uint32_t bB = smb + 65536u + (buf ? 16384u : 0u);
        #pragma unroll
        for (int q = 0; q < 4; q++) {
            int idx = t + 256 * q;
            int row = idx >> 3, slot = idx & 7;
            uint32_t dst = aB + (uint32_t)(row * 128 + ((slot ^ (row & 7)) << 4));
            size_t src = (size_t)(bm * 128 + row) * CD + c * 64 + slot * 8;
            cp_async16(dst,          ah + src);
            cp_async16(dst + 16384u, al + src);
        }
        #pragma unroll
        for (int q = 0; q < 2; q++) {
            int idx = t + 256 * q;
            int row = idx >> 3, slot = idx & 7;
            uint32_t dst = bB + (uint32_t)(row * 128 + ((slot ^ (row & 7)) << 4));
            size_t src = (size_t)(bn * 64 + row) * CD + c * 64 + slot * 8;
            cp_async16(dst,         bh + src);
            cp_async16(dst + 8192u, bl + src);
        }
    };

    float acc[2][4][4] = {};

    prefetch(0, 0); CP_COMMIT();
    prefetch(1, 1); CP_COMMIT();

    #pragma unroll
    for (int c = 0; c < 3; c++) {
        if (c < 2) CP_WAIT(1); else CP_WAIT(0);
        __syncthreads();

        const char* Ah_s = sm + ((c & 1) ? 32768 : 0);
        const char* Al_s = Ah_s + 16384;
        const char* Bh_s = sm + 65536 + ((c & 1) ? 16384 : 0);
        const char* Bl_s = Bh_s + 8192;

        #pragma unroll
        for (int ks = 0; ks < 4; ks++) {
            const uint32_t s0 = (uint32_t)((2 * ks) ^ g) << 4;
            const uint32_t s1 = (uint32_t)((2 * ks + 1) ^ g) << 4;
            const uint32_t tw = (uint32_t)(tg * 4);

            uint32_t Ahf[2][4], Alf[2][4];
            #pragma unroll
            for (int i = 0; i < 2; i++) {
                const uint32_t rb = (uint32_t)((wm * 32 + i * 16 + g) * 128);
                Ahf[i][0] = *(const uint32_t*)(Ah_s + rb + s0 + tw);
                Ahf[i][1] = *(const uint32_t*)(Ah_s + rb + 1024 + s0 + tw);
                Ahf[i][2] = *(const uint32_t*)(Ah_s + rb + s1 + tw);
                Ahf[i][3] = *(const uint32_t*)(Ah_s + rb + 1024 + s1 + tw);
                Alf[i][0] = *(const uint32_t*)(Al_s + rb + s0 + tw);
                Alf[i][1] = *(const uint32_t*)(Al_s + rb + 1024 + s0 + tw);
                Alf[i][2] = *(const uint32_t*)(Al_s + rb + s1 + tw);
                Alf[i][3] = *(const uint32_t*)(Al_s + rb + 1024 + s1 + tw);
            }
            uint32_t Bhf[4][2], Blf[4][2];
            #pragma unroll
            for (int j = 0; j < 4; j++) {
                const uint32_t nb = (uint32_t)((wn * 32 + j * 8 + g) * 128);
                Bhf[j][0] = *(const uint32_t*)(Bh_s + nb + s0 + tw);
                Bhf[j][1] = *(const uint32_t*)(Bh_s + nb + s1 + tw);
                Blf[j][0] = *(const uint32_t*)(Bl_s + nb + s0 + tw);
                Blf[j][1] = *(const uint32_t*)(Bl_s + nb + s1 + tw);
            }
            #pragma unroll
            for (int i = 0; i < 2; i++)
                #pragma unroll
                for (int j = 0; j < 4; j++) {
                    mma_bf16(acc[i][j], Ahf[i], Bhf[j]);
                    mma_bf16(acc[i][j], Ahf[i], Blf[j]);
                    mma_bf16(acc[i][j], Alf[i], Bhf[j]);
                }
        }
        __syncthreads();
        if (c + 2 < 3) { prefetch(c + 2, (c + 2) & 1); CP_COMMIT(); }
    }

    // ---- stage C to smem (stride 68 floats) ----
    #pragma unroll
    for (int i = 0; i < 2; i++) {
        int row0 = wm * 32 + i * 16 + g;
        #pragma unroll
        for (int j = 0; j < 4; j++) {
            int col = wn * 32 + j * 8 + 2 * tg;
            *(float2*)&stage[row0 * 68 + col] =
                make_float2(acc[i][j][0], acc[i][j][1]);
            *(float2*)&stage[(row0 + 8) * 68 + col] =
                make_float2(acc[i][j][2], acc[i][j][3]);
        }
    }
    __syncthreads();

    // ---- epilogue ----
    const int s = t & 15;
    float4 b4 = *(const float4*)(bias + bn * 64 + s * 4);
    #pragma unroll
    for (int it = 0; it < 8; it++) {
        int row = (t >> 4) + 16 * it;
        float4 v = *(float4*)&stage[row * 68 + s * 4];
        v.x += b4.x; v.y += b4.y; v.z += b4.z; v.w += b4.w;
        int m = bm * 128 + row;
        if (QKV) {
            int colg = bn * 64 + s * 4;          // 0..575
            if (bn < 3) {                        // q: scale + bf16
                uint2 o;
                o.x = bf2_of(v.x * ATTN_SCALE, v.y * ATTN_SCALE);
                o.y = bf2_of(v.z * ATTN_SCALE, v.w * ATTN_SCALE);
                *(uint2*)(g_qbf + (size_t)m * CD + colg) = o;
            } else if (bn < 6) {                 // k: bf16
                uint2 o;
                o.x = bf2_of(v.x, v.y);
                o.y = bf2_of(v.z, v.w);
                *(uint2*)(g_kbf + (size_t)m * CD + (colg - CD)) = o;
            } else {                             // v: fp32
                *(float4*)(g_vf + (size_t)m * CD + (colg - 2 * CD)) = v;
            }
        } else {
            int wbv = m >> 6, n = m & 63;
            int b  = wbv >> 8;
            int wh = (wbv >> 4) & 15;
            int ww = wbv & 15;
            int gh = (wh * 8 + (n >> 3) + 4) & 127;
            int gw = (ww * 8 + (n & 7) + 4) & 127;
            *(float4*)(outp + ((size_t)((b * 128 + gh) * 128 + gw)) * CD
                       + bn * 64 + s * 4) = v;
        }
    }
}

// ---------------------------------------------------------------------------
// Kernel 2: tensor-core attention. One window per block, 12 warps.
// smem: sq[64][200 bf16] 25600 | sk 25600 | (raw v fp32 aliases sq+sk)
//       svt_h [192 rows][72 bf16] 27648 @51200 | svt_l 27648 @78848
//       lepe_w 6912 @106496 | lepe_b 768 @113408 -> total 114176 B.
// ---------------------------------------------------------------------------
#define SQ_OFF  0
#define SK_OFF  25600
#define SVT_H   51200
#define SVT_L   78848
#define SWB_OFF 106496
#define SLB_OFF 113408
#define ATTN_SMEM 114176

__global__ __launch_bounds__(384, 2) void attn4(
    const float* __restrict__ prev,
    const float* __restrict__ lepe_w,
    const float* __restrict__ lepe_b,
    float* __restrict__ out)
{
    extern __shared__ char sm[];
    float* sv  = (float*)sm;                  // raw v [n][192] (aliases sq/sk)
    float* swb = (float*)(sm + SWB_OFF);
    float* slb = (float*)(sm + SLB_OFF);

    const int t  = threadIdx.x;
    const int wb = blockIdx.x;

    // ---- load raw v + lepe params ----
    {
        const float4* vsrc = (const float4*)(g_vf + (size_t)wb * NTOK * CD);
        #pragma unroll
        for (int q = 0; q < 8; q++) ((float4*)sv)[t + 384 * q] = vsrc[t + 384 * q];
    }
    for (int idx = t; idx < 9 * CD; idx += 384) swb[idx] = lepe_w[idx];
    if (t < CD) slb[t] = lepe_b[t];
    __syncthreads();

    // ---- LePE; write v' transposed bf16 hi/lo: svt[(h*32+d)*72 + n] ----
    #pragma unroll 4
    for (int q = 0; q < 32; q++) {
        int idx = t + 384 * q;
        int n = idx / CD, c = idx - n * CD;
        int i = n >> 3, j = n & 7;
        float a = slb[c];
        #pragma unroll
        for (int kh = 0; kh < 3; kh++) {
            int ii = i + kh - 1;
            if ((unsigned)ii >= 8u) continue;
            #pragma unroll
            for (int kw = 0; kw < 3; kw++) {
                int jj = j + kw - 1;
                if ((unsigned)jj < 8u)
                    a = fmaf(sv[(ii * 8 + jj) * CD + c],
                             swb[(kh * 3 + kw) * CD + c], a);
            }
        }
        float vp = sv[idx] + a;
        __nv_bfloat16 hb = __float2bfloat16_rn(vp);
        __nv_bfloat16 lb = __float2bfloat16_rn(vp - __bfloat162float(hb));
        int d = c & 31, h = c >> 5;
        ((__nv_bfloat16*)(sm + SVT_H))[(h * 32 + d) * 72 + n] = hb;
        ((__nv_bfloat16*)(sm + SVT_L))[(h * 32 + d) * 72 + n] = lb;
    }
    __syncthreads();

    // ---- load q (pre-scaled bf16) and k into [64][200 bf16] rows ----
    {
        const uint4* qs = (const uint4*)(g_qbf + (size_t)wb * NTOK * CD);
        const uint4* ks = (const uint4*)(g_kbf + (size_t)wb * NTOK * CD);
        #pragma unroll
        for (int q = 0; q < 4; q++) {
            int idx = t + 384 * q;               // < 1536
            int row = idx / 24, slot = idx - row * 24;
            *(uint4*)(sm + SQ_OFF + row * 400 + slot * 16) = qs[idx];
            *(uint4*)(sm + SK_OFF + row * 400 + slot * 16) = ks[idx];
        }
    }
    __syncthreads();

    const int w    = t >> 5;
    const int lane = t & 31;
    const int g    = lane >> 2;
    const int tg   = lane & 3;

    for (int tile = w; tile < 24; tile += 12) {
        const int h  = tile >> 2;
        const int mt = tile & 3;

        // ---- scores: m16 x n64, K=32 (2 k-steps) ----
        float acc[8][4];
        #pragma unroll
        for (int nt = 0; nt < 8; nt++)
            acc[nt][0] = acc[nt][1] = acc[nt][2] = acc[nt][3] = 0.f;
        #pragma unroll
        for (int ks = 0; ks < 2; ks++) {
            const uint32_t kb = (uint32_t)(h * 64 + ks * 32 + tg * 4);
            uint32_t A[4];
            const char* q0 = sm + SQ_OFF + (mt * 16 + g) * 400 + kb;
            A[0] = *(const uint32_t*)(q0);
            A[1] = *(const uint32_t*)(q0 + 8 * 400);
            A[2] = *(const uint32_t*)(q0 + 16);
            A[3] = *(const uint32_t*)(q0 + 8 * 400 + 16);
            #pragma unroll
            for (int nt = 0; nt < 8; nt++) {
                const char* k0 = sm + SK_OFF + (nt * 8 + g) * 400 + kb;
                uint32_t B[2] = { *(const uint32_t*)k0,
                                  *(const uint32_t*)(k0 + 16) };
                mma_bf16(acc[nt], A, B);
            }
        }

        // ---- gate with prev_attn_map ----
        const float* pr = prev + (((size_t)(wb * 6 + h)) * 64 + mt * 16) * 64;
        #pragma unroll
        for (int nt = 0; nt < 8; nt++) {
            float2 p0 = *(const float2*)(pr + g * 64 + nt * 8 + 2 * tg);
            float2 p1 = *(const float2*)(pr + (g + 8) * 64 + nt * 8 + 2 * tg);
            acc[nt][0] *= p0.x; acc[nt][1] *= p0.y;
            acc[nt][2] *= p1.x; acc[nt][3] *= p1.y;
        }

        // ---- softmax: rows g (c0,c1) and g+8 (c2,c3), quad reduction ----
        float m0 = -1e30f, m1 = -1e30f;
        #pragma unroll
        for (int nt = 0; nt < 8; nt++) {
            m0 = fmaxf(m0, fmaxf(acc[nt][0], acc[nt][1]));
            m1 = fmaxf(m1, fmaxf(acc[nt][2], acc[nt][3]));
        }
        m0 = fmaxf(m0, __shfl_xor_sync(0xffffffffu, m0, 1));
        m0 = fmaxf(m0, __shfl_xor_sync(0xffffffffu, m0, 2));
        m1 = fmaxf(m1, __shfl_xor_sync(0xffffffffu, m1, 1));
        m1 = fmaxf(m1, __shfl_xor_sync(0xffffffffu, m1, 2));
        float s0 = 0.f, s1 = 0.f;
        #pragma unroll
        for (int nt = 0; nt < 8; nt++) {
            acc[nt][0] = __expf(acc[nt][0] - m0);
            acc[nt][1] = __expf(acc[nt][1] - m0);
            acc[nt][2] = __expf(acc[nt][2] - m1);
            acc[nt][3] = __expf(acc[nt][3] - m1);
            s0 += acc[nt][0] + acc[nt][1];
            s1 += acc[nt][2] + acc[nt][3];
        }
        s0 += __shfl_xor_sync(0xffffffffu, s0, 1);
        s0 += __shfl_xor_sync(0xffffffffu, s0, 2);
        s1 += __shfl_xor_sync(0xffffffffu, s1, 1);
        s1 += __shfl_xor_sync(0xffffffffu, s1, 2);
        const float i0 = 1.0f / s0, i1 = 1.0f / s1;

        // ---- normalize + write attn ----
        float* ao = out + OUT_ELEMS + (((size_t)(wb * 6 + h)) * 64 + mt * 16) * 64;
        #pragma unroll
        for (int nt = 0; nt < 8; nt++) {
            acc[nt][0] *= i0; acc[nt][1] *= i0;
            acc[nt][2] *= i1; acc[nt][3] *= i1;
            *(float2*)(ao + g * 64 + nt * 8 + 2 * tg) =
                make_float2(acc[nt][0], acc[nt][1]);
            *(float2*)(ao + (g + 8) * 64 + nt * 8 + 2 * tg) =
                make_float2(acc[nt][2], acc[nt][3]);
        }

        // ---- AV: attn (16x64) @ v' (64x32), 4 k-steps of 16 ----
        float acc2[4][4];
        #pragma unroll
        for (int nt = 0; nt < 4; nt++)
            acc2[nt][0] = acc2[nt][1] = acc2[nt][2] = acc2[nt][3] = 0.f;
        #pragma unroll
        for (int ks = 0; ks < 4; ks++) {
            const int j0 = 2 * ks, j1 = 2 * ks + 1;
            uint32_t Ahf[4], Alf[4];
            Ahf[0] = bf2_of(acc[j0][0], acc[j0][1]);
            Alf[0] = bf2_lo_of(acc[j0][0], acc[j0][1], Ahf[0]);
            Ahf[1] = bf2_of(acc[j0][2], acc[j0][3]);
            Alf[1] = bf2_lo_of(acc[j0][2], acc[j0][3], Ahf[1]);
            Ahf[2] = bf2_of(acc[j1][0], acc[j1][1]);
            Alf[2] = bf2_lo_of(acc[j1][0], acc[j1][1], Ahf[2]);
            Ahf[3] = bf2_of(acc[j1][2], acc[j1][3]);
            Alf[3] = bf2_lo_of(acc[j1][2], acc[j1][3], Ahf[3]);
            const uint32_t jb = (uint32_t)(ks * 32 + tg * 4);
            #pragma unroll
            for (int nt = 0; nt < 4; nt++) {
                const char* vh = sm + SVT_H + (h * 32 + nt * 8 + g) * 144 + jb;
                const char* vl = sm + SVT_L + (h * 32 + nt * 8 + g) * 144 + jb;
                uint32_t Bh2[2] = { *(const uint32_t*)vh,
                                    *(const uint32_t*)(vh + 16) };
                uint32_t Bl2[2] = { *(const uint32_t*)vl,
                                    *(const uint32_t*)(vl + 16) };
                mma_bf16(acc2[nt], Ahf, Bh2);
                mma_bf16(acc2[nt], Ahf, Bl2);
                mma_bf16(acc2[nt], Alf, Bh2);
            }
        }

        // ---- write attn@v' output as bf16 hi/lo for proj ----
        const size_t r0 = (size_t)(wb * 64 + mt * 16 + g) * CD + h * 32;
        const size_t r1 = r0 + 8 * CD;
        #pragma unroll
        for (int nt = 0; nt < 4; nt++) {
            int col = nt * 8 + 2 * tg;
            uint32_t h0 = bf2_of(acc2[nt][0], acc2[nt][1]);
            uint32_t l0 = bf2_lo_of(acc2[nt][0], acc2[nt][1], h0);
            uint32_t h1 = bf2_of(acc2[nt][2], acc2[nt][3]);
            uint32_t l1 = bf2_lo_of(acc2[nt][2], acc2[nt][3], h1);
            *(uint32_t*)(g_avh + r0 + col) = h0;
            *(uint32_t*)(g_avl + r0 + col) = l0;
            *(uint32_t*)(g_avh + r1 + col) = h1;
            *(uint32_t*)(g_avl + r1 + col) = l1;
        }
    }
}

// ---------------------------------------------------------------------------
extern "C" void kernel_launch(void* const* d_in, const int* in_sizes, int n_in,
                              void* d_out, int out_size)
{
    const float* x      = (const float*)d_in[0];
    const float* prev   = (const float*)d_in[1];
    const float* qkv_w  = (const float*)d_in[2];
    const float* qkv_b  = (const float*)d_in[3];
    const float* proj_w = (const float*)d_in[4];
    const float* proj_b = (const float*)d_in[5];
    const float* lepe_w = (const float*)d_in[6];
    const float* lepe_b = (const float*)d_in[7];
    float* out = (float*)d_out;

    cudaFuncSetAttribute(attn4,
                         cudaFuncAttributeMaxDynamicSharedMemorySize, ATTN_SMEM);
    cudaFuncSetAttribute(mma_gemm<true>,
                         cudaFuncAttributeMaxDynamicSharedMemorySize, MM_SMEM);
    cudaFuncSetAttribute(mma_gemm<false>,
                         cudaFuncAttributeMaxDynamicSharedMemorySize, MM_SMEM);

    prep_w<<<576, 256>>>(qkv_w, proj_w);
    prep_x<<<12288, 256>>>(x);
    mma_gemm<true><<<dim3(512, 9), 256, MM_SMEM>>>(qkv_b, nullptr);
    attn4<<<NWIN, 384, ATTN_SMEM>>>(prev, lepe_w, lepe_b, out);
    mma_gemm<false><<<dim3(512, 3), 256, MM_SMEM>>>(proj_b, out);
}

// round 11
// speedup vs baseline: 3.0624x; 1.0815x over previous
#include <cuda_runtime.h>
#include <cuda_bf16.h>
#include <math.h>
#include <stdint.h>

#define NWIN 1024
#define NTOK 64
#define CD   192
#define C3   576
#define NROW 65536
#define OUT_ELEMS 12582912
#define ATTN_SCALE 0.17677669529663687f

// ---------------- device scratch ----------------
static __device__ __align__(16) __nv_bfloat16 g_qbf[NROW * CD];  // q, bias+scaled
static __device__ __align__(16) __nv_bfloat16 g_kbf[NROW * CD];  // k, bias
static __device__ __align__(16) float         g_vf [NROW * CD];  // v fp32
static __device__ __align__(16) __nv_bfloat16 g_xh[NROW * CD];
static __device__ __align__(16) __nv_bfloat16 g_xl[NROW * CD];
static __device__ __align__(16) __nv_bfloat16 g_avh[NROW * CD];
static __device__ __align__(16) __nv_bfloat16 g_avl[NROW * CD];
static __device__ __align__(16) __nv_bfloat16 g_wt_hi[C3 * CD];
static __device__ __align__(16) __nv_bfloat16 g_wt_lo[C3 * CD];
static __device__ __align__(16) __nv_bfloat16 g_pt_hi[CD * CD];
static __device__ __align__(16) __nv_bfloat16 g_pt_lo[CD * CD];

// ---------------- PTX helpers ----------------
__device__ __forceinline__ uint32_t smem_u32(const void* p) {
    uint32_t a;
    asm("{ .reg .u64 t; cvta.to.shared.u64 t, %1; cvt.u32.u64 %0, t; }"
        : "=r"(a) : "l"(p));
    return a;
}
__device__ __forceinline__ void mma_bf16(float* c, const uint32_t* a,
                                         const uint32_t* b) {
    asm volatile(
        "mma.sync.aligned.m16n8k16.row.col.f32.bf16.bf16.f32 "
        "{%0,%1,%2,%3}, {%4,%5,%6,%7}, {%8,%9}, {%0,%1,%2,%3};"
        : "+f"(c[0]), "+f"(c[1]), "+f"(c[2]), "+f"(c[3])
        : "r"(a[0]), "r"(a[1]), "r"(a[2]), "r"(a[3]), "r"(b[0]), "r"(b[1]));
}
__device__ __forceinline__ void cp_async16(uint32_t dst, const void* src) {
    asm volatile("cp.async.cg.shared.global [%0], [%1], 16;\n"
                 :: "r"(dst), "l"(src));
}
#define CP_COMMIT() asm volatile("cp.async.commit_group;\n" ::: "memory")
#define CP_WAIT(n)  asm volatile("cp.async.wait_group %0;\n" :: "n"(n) : "memory")

__device__ __forceinline__ uint32_t bf2_of(float x, float y) {
    __nv_bfloat162 h = __float22bfloat162_rn(make_float2(x, y));
    return *(uint32_t*)&h;
}
__device__ __forceinline__ uint32_t bf2_lo_of(float x, float y, uint32_t hi) {
    __nv_bfloat162 hb = *(__nv_bfloat162*)&hi;
    float2 hf = __bfloat1622float2(hb);
    __nv_bfloat162 l = __float22bfloat162_rn(make_float2(x - hf.x, y - hf.y));
    return *(uint32_t*)&l;
}

// ---------------------------------------------------------------------------
// Kernel 0a: weight pre-transpose + bf16 hi/lo split.
// ---------------------------------------------------------------------------
__global__ __launch_bounds__(256) void prep_w(const float* __restrict__ qkv_w,
                                              const float* __restrict__ proj_w)
{
    int idx = blockIdx.x * 256 + threadIdx.x;
    if (idx < C3 * CD) {
        int n = idx / CD, k = idx - n * CD;
        float v = qkv_w[k * C3 + n];
        __nv_bfloat16 h = __float2bfloat16_rn(v);
        g_wt_hi[idx] = h;
        g_wt_lo[idx] = __float2bfloat16_rn(v - __bfloat162float(h));
    } else {
        int j = idx - C3 * CD;
        if (j < CD * CD) {
            int n = j / CD, k = j - n * CD;
            float v = proj_w[k * CD + n];
            __nv_bfloat16 h = __float2bfloat16_rn(v);
            g_pt_hi[j] = h;
            g_pt_lo[j] = __float2bfloat16_rn(v - __bfloat162float(h));
        }
    }
}

// ---------------------------------------------------------------------------
// Kernel 0b: shifted-window gather of x + bf16 hi/lo split.
// ---------------------------------------------------------------------------
__global__ __launch_bounds__(256) void prep_x(const float* __restrict__ x)
{
    int idx = blockIdx.x * 256 + threadIdx.x;
    int m  = idx / 48;
    int c4 = idx - m * 48;
    int wbv = m >> 6, n = m & 63;
    int b  = wbv >> 8;
    int wh = (wbv >> 4) & 15;
    int ww = wbv & 15;
    int gh = (wh * 8 + (n >> 3) + 4) & 127;
    int gw = (ww * 8 + (n & 7) + 4) & 127;
    float4 v = *(const float4*)(x + ((size_t)((b * 128 + gh) * 128 + gw)) * CD
                                + c4 * 4);
    __nv_bfloat162 h01 = __float22bfloat162_rn(make_float2(v.x, v.y));
    __nv_bfloat162 h23 = __float22bfloat162_rn(make_float2(v.z, v.w));
    float2 f01 = __bfloat1622float2(h01);
    float2 f23 = __bfloat1622float2(h23);
    __nv_bfloat162 l01 = __float22bfloat162_rn(make_float2(v.x - f01.x, v.y - f01.y));
    __nv_bfloat162 l23 = __float22bfloat162_rn(make_float2(v.z - f23.x, v.w - f23.y));
    uint2 hh, ll;
    hh.x = *(uint32_t*)&h01; hh.y = *(uint32_t*)&h23;
    ll.x = *(uint32_t*)&l01; ll.y = *(uint32_t*)&l23;
    *(uint2*)(g_xh + (size_t)m * CD + c4 * 4) = hh;
    *(uint2*)(g_xl + (size_t)m * CD + c4 * 4) = ll;
}

// ---------------------------------------------------------------------------
// mma.sync GEMM with cp.async double buffering.
// MODE 0: q,k columns of qkv, SINGLE-pass bf16 (q/k stored bf16 anyway).
// MODE 1: v columns of qkv, bf16x3, fp32 out.
// MODE 2: proj, bf16x3, scatter to output.
// ---------------------------------------------------------------------------
#define MM_SMEM 98304

template<int MODE>
__global__ __launch_bounds__(256, 2) void mma_gemm(
    const float* __restrict__ bias,
    float* __restrict__ outp)
{
    extern __shared__ char sm[];
    const uint32_t smb = smem_u32(sm);
    float* stage = (float*)sm;

    constexpr bool X3   = (MODE != 0);       // use lo terms
    constexpr int  BNOFF = (MODE == 1) ? 6 : 0;

    const __nv_bfloat16* ah = (MODE == 2) ? g_avh : g_xh;
    const __nv_bfloat16* al = (MODE == 2) ? g_avl : g_xl;
    const __nv_bfloat16* bhp = (MODE == 2) ? g_pt_hi : g_wt_hi;
    const __nv_bfloat16* blp = (MODE == 2) ? g_pt_lo : g_wt_lo;

    const int t    = threadIdx.x;
    const int w    = t >> 5;
    const int lane = t & 31;
    const int bm   = blockIdx.x;
    const int bn   = blockIdx.y;
    const int wm   = w >> 1;
    const int wn   = w & 1;
    const int g    = lane >> 2;
    const int tg   = lane & 3;

    auto prefetch = [&](int c, int buf) {
        const uint32_t aB = smb + (buf ? 32768u : 0u);
        const uint32_t bB = smb + 65536u + (buf ? 16384u : 0u);
        #pragma unroll
        for (int q = 0; q < 4; q++) {
            int idx = t + 256 * q;
            int row = idx >> 3, slot = idx & 7;
            uint32_t dst = aB + (uint32_t)(row * 128 + ((slot ^ (row & 7)) << 4));
            size_t src = (size_t)(bm * 128 + row) * CD + c * 64 + slot * 8;
            cp_async16(dst, ah + src);
            if (X3) cp_async16(dst + 16384u, al + src);
        }
        #pragma unroll
        for (int q = 0; q < 2; q++) {
            int idx = t + 256 * q;
            int row = idx >> 3, slot = idx & 7;
            uint32_t dst = bB + (uint32_t)(row * 128 + ((slot ^ (row & 7)) << 4));
            size_t src = (size_t)((BNOFF + bn) * 64 + row) * CD + c * 64 + slot * 8;
            cp_async16(dst, bhp + src);
            if (X3) cp_async16(dst + 8192u, blp + src);
        }
    };

    float acc[2][4][4] = {};

    prefetch(0, 0); CP_COMMIT();
    prefetch(1, 1); CP_COMMIT();

    #pragma unroll
    for (int c = 0; c < 3; c++) {
        if (c < 2) CP_WAIT(1); else CP_WAIT(0);
        __syncthreads();

        const char* Ah_s = sm + ((c & 1) ? 32768 : 0);
        const char* Al_s = Ah_s + 16384;
        const char* Bh_s = sm + 65536 + ((c & 1) ? 16384 : 0);
        const char* Bl_s = Bh_s + 8192;

        #pragma unroll
        for (int ks = 0; ks < 4; ks++) {
            const uint32_t s0 = (uint32_t)((2 * ks) ^ g) << 4;
            const uint32_t s1 = (uint32_t)((2 * ks + 1) ^ g) << 4;
            const uint32_t tw = (uint32_t)(tg * 4);

            uint32_t Ahf[2][4], Alf[2][4];
            #pragma unroll
            for (int i = 0; i < 2; i++) {
                const uint32_t rb = (uint32_t)((wm * 32 + i * 16 + g) * 128);
                Ahf[i][0] = *(const uint32_t*)(Ah_s + rb + s0 + tw);
                Ahf[i][1] = *(const uint32_t*)(Ah_s + rb + 1024 + s0 + tw);
                Ahf[i][2] = *(const uint32_t*)(Ah_s + rb + s1 + tw);
                Ahf[i][3] = *(const uint32_t*)(Ah_s + rb + 1024 + s1 + tw);
                if (X3) {
                    Alf[i][0] = *(const uint32_t*)(Al_s + rb + s0 + tw);
                    Alf[i][1] = *(const uint32_t*)(Al_s + rb + 1024 + s0 + tw);
                    Alf[i][2] = *(const uint32_t*)(Al_s + rb + s1 + tw);
                    Alf[i][3] = *(const uint32_t*)(Al_s + rb + 1024 + s1 + tw);
                }
            }
            uint32_t Bhf[4][2], Blf[4][2];
            #pragma unroll
            for (int j = 0; j < 4; j++) {
                const uint32_t nb = (uint32_t)((wn * 32 + j * 8 + g) * 128);
                Bhf[j][0] = *(const uint32_t*)(Bh_s + nb + s0 + tw);
                Bhf[j][1] = *(const uint32_t*)(Bh_s + nb + s1 + tw);
                if (X3) {
                    Blf[j][0] = *(const uint32_t*)(Bl_s + nb + s0 + tw);
                    Blf[j][1] = *(const uint32_t*)(Bl_s + nb + s1 + tw);
                }
            }
            #pragma unroll
            for (int i = 0; i < 2; i++)
                #pragma unroll
                for (int j = 0; j < 4; j++) {
                    mma_bf16(acc[i][j], Ahf[i], Bhf[j]);
                    if (X3) {
                        mma_bf16(acc[i][j], Ahf[i], Blf[j]);
                        mma_bf16(acc[i][j], Alf[i], Bhf[j]);
                    }
                }
        }
        __syncthreads();
        if (c + 2 < 3) { prefetch(c + 2, (c + 2) & 1); CP_COMMIT(); }
    }

    // ---- stage C to smem (stride 68 floats) ----
    #pragma unroll
    for (int i = 0; i < 2; i++) {
        int row0 = wm * 32 + i * 16 + g;
        #pragma unroll
        for (int j = 0; j < 4; j++) {
            int col = wn * 32 + j * 8 + 2 * tg;
            *(float2*)&stage[row0 * 68 + col] =
                make_float2(acc[i][j][0], acc[i][j][1]);
            *(float2*)&stage[(row0 + 8) * 68 + col] =
                make_float2(acc[i][j][2], acc[i][j][3]);
        }
    }
    __syncthreads();

    // ---- epilogue ----
    const int s = t & 15;
    float4 b4 = *(const float4*)(bias + (BNOFF + bn) * 64 + s * 4);
    #pragma unroll
    for (int it = 0; it < 8; it++) {
        int row = (t >> 4) + 16 * it;
        float4 v = *(float4*)&stage[row * 68 + s * 4];
        v.x += b4.x; v.y += b4.y; v.z += b4.z; v.w += b4.w;
        int m = bm * 128 + row;
        if (MODE == 0) {
            int colg = bn * 64 + s * 4;          // 0..383
            if (colg < CD) {                     // q: scale + bf16
                uint2 o;
                o.x = bf2_of(v.x * ATTN_SCALE, v.y * ATTN_SCALE);
                o.y = bf2_of(v.z * ATTN_SCALE, v.w * ATTN_SCALE);
                *(uint2*)(g_qbf + (size_t)m * CD + colg) = o;
            } else {                             // k: bf16
                uint2 o;
                o.x = bf2_of(v.x, v.y);
                o.y = bf2_of(v.z, v.w);
                *(uint2*)(g_kbf + (size_t)m * CD + (colg - CD)) = o;
            }
        } else if (MODE == 1) {                  // v: fp32
            *(float4*)(g_vf + (size_t)m * CD + bn * 64 + s * 4) = v;
        } else {
            int wbv = m >> 6, n = m & 63;
            int b  = wbv >> 8;
            int wh = (wbv >> 4) & 15;
            int ww = wbv & 15;
            int gh = (wh * 8 + (n >> 3) + 4) & 127;
            int gw = (ww * 8 + (n & 7) + 4) & 127;
            *(float4*)(outp + ((size_t)((b * 128 + gh) * 128 + gw)) * CD
                       + bn * 64 + s * 4) = v;
        }
    }
}

// ---------------------------------------------------------------------------
// Kernel 2: tensor-core attention (unchanged from round 10, passing).
// ---------------------------------------------------------------------------
#define SQ_OFF  0
#define SK_OFF  25600
#define SVT_H   51200
#define SVT_L   78848
#define SWB_OFF 106496
#define SLB_OFF 113408
#define ATTN_SMEM 114176

__global__ __launch_bounds__(384, 2) void attn4(
    const float* __restrict__ prev,
    const float* __restrict__ lepe_w,
    const float* __restrict__ lepe_b,
    float* __restrict__ out)
{
    extern __shared__ char sm[];
    float* sv  = (float*)sm;
    float* swb = (float*)(sm + SWB_OFF);
    float* slb = (float*)(sm + SLB_OFF);

    const int t  = threadIdx.x;
    const int wb = blockIdx.x;

    {
        const float4* vsrc = (const float4*)(g_vf + (size_t)wb * NTOK * CD);
        #pragma unroll
        for (int q = 0; q < 8; q++) ((float4*)sv)[t + 384 * q] = vsrc[t + 384 * q];
    }
    for (int idx = t; idx < 9 * CD; idx += 384) swb[idx] = lepe_w[idx];
    if (t < CD) slb[t] = lepe_b[t];
    __syncthreads();

    #pragma unroll 4
    for (int q = 0; q < 32; q++) {
        int idx = t + 384 * q;
        int n = idx / CD, c = idx - n * CD;
        int i = n >> 3, j = n & 7;
        float a = slb[c];
        #pragma unroll
        for (int kh = 0; kh < 3; kh++) {
            int ii = i + kh - 1;
            if ((unsigned)ii >= 8u) continue;
            #pragma unroll
            for (int kw = 0; kw < 3; kw++) {
                int jj = j + kw - 1;
                if ((unsigned)jj < 8u)
                    a = fmaf(sv[(ii * 8 + jj) * CD + c],
                             swb[(kh * 3 + kw) * CD + c], a);
            }
        }
        float vp = sv[idx] + a;
        __nv_bfloat16 hb = __float2bfloat16_rn(vp);
        __nv_bfloat16 lb = __float2bfloat16_rn(vp - __bfloat162float(hb));
        int d = c & 31, h = c >> 5;
        ((__nv_bfloat16*)(sm + SVT_H))[(h * 32 + d) * 72 + n] = hb;
        ((__nv_bfloat16*)(sm + SVT_L))[(h * 32 + d) * 72 + n] = lb;
    }
    __syncthreads();

    {
        const uint4* qs = (const uint4*)(g_qbf + (size_t)wb * NTOK * CD);
        const uint4* ks = (const uint4*)(g_kbf + (size_t)wb * NTOK * CD);
        #pragma unroll
        for (int q = 0; q < 4; q++) {
            int idx = t + 384 * q;
            int row = idx / 24, slot = idx - row * 24;
            *(uint4*)(sm + SQ_OFF + row * 400 + slot * 16) = qs[idx];
            *(uint4*)(sm + SK_OFF + row * 400 + slot * 16) = ks[idx];
        }
    }
    __syncthreads();

    const int w    = t >> 5;
    const int lane = t & 31;
    const int g    = lane >> 2;
    const int tg   = lane & 3;

    for (int tile = w; tile < 24; tile += 12) {
        const int h  = tile >> 2;
        const int mt = tile & 3;

        float acc[8][4];
        #pragma unroll
        for (int nt = 0; nt < 8; nt++)
            acc[nt][0] = acc[nt][1] = acc[nt][2] = acc[nt][3] = 0.f;
        #pragma unroll
        for (int ks = 0; ks < 2; ks++) {
            const uint32_t kb = (uint32_t)(h * 64 + ks * 32 + tg * 4);
            uint32_t A[4];
            const char* q0 = sm + SQ_OFF + (mt * 16 + g) * 400 + kb;
            A[0] = *(const uint32_t*)(q0);
            A[1] = *(const uint32_t*)(q0 + 8 * 400);
            A[2] = *(const uint32_t*)(q0 + 16);
            A[3] = *(const uint32_t*)(q0 + 8 * 400 + 16);
            #pragma unroll
            for (int nt = 0; nt < 8; nt++) {
                const char* k0 = sm + SK_OFF + (nt * 8 + g) * 400 + kb;
                uint32_t B[2] = { *(const uint32_t*)k0,
                                  *(const uint32_t*)(k0 + 16) };
                mma_bf16(acc[nt], A, B);
            }
        }

        const float* pr = prev + (((size_t)(wb * 6 + h)) * 64 + mt * 16) * 64;
        #pragma unroll
        for (int nt = 0; nt < 8; nt++) {
            float2 p0 = *(const float2*)(pr + g * 64 + nt * 8 + 2 * tg);
            float2 p1 = *(const float2*)(pr + (g + 8) * 64 + nt * 8 + 2 * tg);
            acc[nt][0] *= p0.x; acc[nt][1] *= p0.y;
            acc[nt][2] *= p1.x; acc[nt][3] *= p1.y;
        }

        float m0 = -1e30f, m1 = -1e30f;
        #pragma unroll
        for (int nt = 0; nt < 8; nt++) {
            m0 = fmaxf(m0, fmaxf(acc[nt][0], acc[nt][1]));
            m1 = fmaxf(m1, fmaxf(acc[nt][2], acc[nt][3]));
        }
        m0 = fmaxf(m0, __shfl_xor_sync(0xffffffffu, m0, 1));
        m0 = fmaxf(m0, __shfl_xor_sync(0xffffffffu, m0, 2));
        m1 = fmaxf(m1, __shfl_xor_sync(0xffffffffu, m1, 1));
        m1 = fmaxf(m1, __shfl_xor_sync(0xffffffffu, m1, 2));
        float s0 = 0.f, s1 = 0.f;
        #pragma unroll
        for (int nt = 0; nt < 8; nt++) {
            acc[nt][0] = __expf(acc[nt][0] - m0);
            acc[nt][1] = __expf(acc[nt][1] - m0);
            acc[nt][2] = __expf(acc[nt][2] - m1);
            acc[nt][3] = __expf(acc[nt][3] - m1);
            s0 += acc[nt][0] + acc[nt][1];
            s1 += acc[nt][2] + acc[nt][3];
        }
        s0 += __shfl_xor_sync(0xffffffffu, s0, 1);
        s0 += __shfl_xor_sync(0xffffffffu, s0, 2);
        s1 += __shfl_xor_sync(0xffffffffu, s1, 1);
        s1 += __shfl_xor_sync(0xffffffffu, s1, 2);
        const float i0 = 1.0f / s0, i1 = 1.0f / s1;

        float* ao = out + OUT_ELEMS + (((size_t)(wb * 6 + h)) * 64 + mt * 16) * 64;
        #pragma unroll
        for (int nt = 0; nt < 8; nt++) {
            acc[nt][0] *= i0; acc[nt][1] *= i0;
            acc[nt][2] *= i1; acc[nt][3] *= i1;
            *(float2*)(ao + g * 64 + nt * 8 + 2 * tg) =
                make_float2(acc[nt][0], acc[nt][1]);
            *(float2*)(ao + (g + 8) * 64 + nt * 8 + 2 * tg) =
                make_float2(acc[nt][2], acc[nt][3]);
        }

        float acc2[4][4];
        #pragma unroll
        for (int nt = 0; nt < 4; nt++)
            acc2[nt][0] = acc2[nt][1] = acc2[nt][2] = acc2[nt][3] = 0.f;
        #pragma unroll
        for (int ks = 0; ks < 4; ks++) {
            const int j0 = 2 * ks, j1 = 2 * ks + 1;
            uint32_t Ahf[4], Alf[4];
            Ahf[0] = bf2_of(acc[j0][0], acc[j0][1]);
            Alf[0] = bf2_lo_of(acc[j0][0], acc[j0][1], Ahf[0]);
            Ahf[1] = bf2_of(acc[j0][2], acc[j0][3]);
            Alf[1] = bf2_lo_of(acc[j0][2], acc[j0][3], Ahf[1]);
            Ahf[2] = bf2_of(acc[j1][0], acc[j1][1]);
            Alf[2] = bf2_lo_of(acc[j1][0], acc[j1][1], Ahf[2]);
            Ahf[3] = bf2_of(acc[j1][2], acc[j1][3]);
            Alf[3] = bf2_lo_of(acc[j1][2], acc[j1][3], Ahf[3]);
            const uint32_t jb = (uint32_t)(ks * 32 + tg * 4);
            #pragma unroll
            for (int nt = 0; nt < 4; nt++) {
                const char* vh = sm + SVT_H + (h * 32 + nt * 8 + g) * 144 + jb;
                const char* vl = sm + SVT_L + (h * 32 + nt * 8 + g) * 144 + jb;
                uint32_t Bh2[2] = { *(const uint32_t*)vh,
                                    *(const uint32_t*)(vh + 16) };
                uint32_t Bl2[2] = { *(const uint32_t*)vl,
                                    *(const uint32_t*)(vl + 16) };
                mma_bf16(acc2[nt], Ahf, Bh2);
                mma_bf16(acc2[nt], Ahf, Bl2);
                mma_bf16(acc2[nt], Alf, Bh2);
            }
        }

        const size_t r0 = (size_t)(wb * 64 + mt * 16 + g) * CD + h * 32;
        const size_t r1 = r0 + 8 * CD;
        #pragma unroll
        for (int nt = 0; nt < 4; nt++) {
            int col = nt * 8 + 2 * tg;
            uint32_t h0 = bf2_of(acc2[nt][0], acc2[nt][1]);
            uint32_t l0 = bf2_lo_of(acc2[nt][0], acc2[nt][1], h0);
            uint32_t h1 = bf2_of(acc2[nt][2], acc2[nt][3]);
            uint32_t l1 = bf2_lo_of(acc2[nt][2], acc2[nt][3], h1);
            *(uint32_t*)(g_avh + r0 + col) = h0;
            *(uint32_t*)(g_avl + r0 + col) = l0;
            *(uint32_t*)(g_avh + r1 + col) = h1;
            *(uint32_t*)(g_avl + r1 + col) = l1;
        }
    }
}

// ---------------------------------------------------------------------------
extern "C" void kernel_launch(void* const* d_in, const int* in_sizes, int n_in,
                              void* d_out, int out_size)
{
    const float* x      = (const float*)d_in[0];
    const float* prev   = (const float*)d_in[1];
    const float* qkv_w  = (const float*)d_in[2];
    const float* qkv_b  = (const float*)d_in[3];
    const float* proj_w = (const float*)d_in[4];
    const float* proj_b = (const float*)d_in[5];
    const float* lepe_w = (const float*)d_in[6];
    const float* lepe_b = (const float*)d_in[7];
    float* out = (float*)d_out;

    cudaFuncSetAttribute(attn4,
                         cudaFuncAttributeMaxDynamicSharedMemorySize, ATTN_SMEM);
    cudaFuncSetAttribute(mma_gemm<0>,
                         cudaFuncAttributeMaxDynamicSharedMemorySize, MM_SMEM);
    cudaFuncSetAttribute(mma_gemm<1>,
                         cudaFuncAttributeMaxDynamicSharedMemorySize, MM_SMEM);
    cudaFuncSetAttribute(mma_gemm<2>,
                         cudaFuncAttributeMaxDynamicSharedMemorySize, MM_SMEM);

    prep_w<<<576, 256>>>(qkv_w, proj_w);
    prep_x<<<12288, 256>>>(x);
    mma_gemm<0><<<dim3(512, 6), 256, MM_SMEM>>>(qkv_b, nullptr);   // q,k single-pass
    mma_gemm<1><<<dim3(512, 3), 256, MM_SMEM>>>(qkv_b, nullptr);   // v x3
    attn4<<<NWIN, 384, ATTN_SMEM>>>(prev, lepe_w, lepe_b, out);
    mma_gemm<2><<<dim3(512, 3), 256, MM_SMEM>>>(proj_b, out);      // proj x3
}

// round 12
// speedup vs baseline: 3.4585x; 1.1294x over previous
#include <cuda_runtime.h>
#include <cuda_bf16.h>
#include <math.h>
#include <stdint.h>

#define NWIN 1024
#define NTOK 64
#define CD   192
#define C3   576
#define NROW 65536
#define OUT_ELEMS 12582912
#define ATTN_SCALE 0.17677669529663687f

// ---------------- device scratch ----------------
static __device__ __align__(16) __nv_bfloat16 g_qbf[NROW * CD];  // q, bias+scaled
static __device__ __align__(16) __nv_bfloat16 g_kbf[NROW * CD];  // k, bias
static __device__ __align__(16) __nv_bfloat16 g_vth[NROW * CD];  // v'^T per window, hi
static __device__ __align__(16) __nv_bfloat16 g_vtl[NROW * CD];  // v'^T per window, lo
static __device__ __align__(16) __nv_bfloat16 g_xh[NROW * CD];
static __device__ __align__(16) __nv_bfloat16 g_xl[NROW * CD];
static __device__ __align__(16) __nv_bfloat16 g_avh[NROW * CD];
static __device__ __align__(16) __nv_bfloat16 g_avl[NROW * CD];
static __device__ __align__(16) __nv_bfloat16 g_wt_hi[C3 * CD];
static __device__ __align__(16) __nv_bfloat16 g_wt_lo[C3 * CD];
static __device__ __align__(16) __nv_bfloat16 g_pt_hi[CD * CD];
static __device__ __align__(16) __nv_bfloat16 g_pt_lo[CD * CD];

// ---------------- PTX helpers ----------------
__device__ __forceinline__ uint32_t smem_u32(const void* p) {
    uint32_t a;
    asm("{ .reg .u64 t; cvta.to.shared.u64 t, %1; cvt.u32.u64 %0, t; }"
        : "=r"(a) : "l"(p));
    return a;
}
__device__ __forceinline__ void mma_bf16(float* c, const uint32_t* a,
                                         const uint32_t* b) {
    asm volatile(
        "mma.sync.aligned.m16n8k16.row.col.f32.bf16.bf16.f32 "
        "{%0,%1,%2,%3}, {%4,%5,%6,%7}, {%8,%9}, {%0,%1,%2,%3};"
        : "+f"(c[0]), "+f"(c[1]), "+f"(c[2]), "+f"(c[3])
        : "r"(a[0]), "r"(a[1]), "r"(a[2]), "r"(a[3]), "r"(b[0]), "r"(b[1]));
}
__device__ __forceinline__ void cp_async16(uint32_t dst, const void* src) {
    asm volatile("cp.async.cg.shared.global [%0], [%1], 16;\n"
                 :: "r"(dst), "l"(src));
}
#define CP_COMMIT() asm volatile("cp.async.commit_group;\n" ::: "memory")
#define CP_WAIT(n)  asm volatile("cp.async.wait_group %0;\n" :: "n"(n) : "memory")

__device__ __forceinline__ uint32_t bf2_of(float x, float y) {
    __nv_bfloat162 h = __float22bfloat162_rn(make_float2(x, y));
    return *(uint32_t*)&h;
}
__device__ __forceinline__ uint32_t bf2_lo_of(float x, float y, uint32_t hi) {
    __nv_bfloat162 hb = *(__nv_bfloat162*)&hi;
    float2 hf = __bfloat1622float2(hb);
    __nv_bfloat162 l = __float22bfloat162_rn(make_float2(x - hf.x, y - hf.y));
    return *(uint32_t*)&l;
}

// ---------------------------------------------------------------------------
// Kernel 0a: weight pre-transpose + bf16 hi/lo split.
// ---------------------------------------------------------------------------
__global__ __launch_bounds__(256) void prep_w(const float* __restrict__ qkv_w,
                                              const float* __restrict__ proj_w)
{
    int idx = blockIdx.x * 256 + threadIdx.x;
    if (idx < C3 * CD) {
        int n = idx / CD, k = idx - n * CD;
        float v = qkv_w[k * C3 + n];
        __nv_bfloat16 h = __float2bfloat16_rn(v);
        g_wt_hi[idx] = h;
        g_wt_lo[idx] = __float2bfloat16_rn(v - __bfloat162float(h));
    } else {
        int j = idx - C3 * CD;
        if (j < CD * CD) {
            int n = j / CD, k = j - n * CD;
            float v = proj_w[k * CD + n];
            __nv_bfloat16 h = __float2bfloat16_rn(v);
            g_pt_hi[j] = h;
            g_pt_lo[j] = __float2bfloat16_rn(v - __bfloat162float(h));
        }
    }
}

// ---------------------------------------------------------------------------
// Kernel 0b: shifted-window gather of x + bf16 hi/lo split.
// ---------------------------------------------------------------------------
__global__ __launch_bounds__(256) void prep_x(const float* __restrict__ x)
{
    int idx = blockIdx.x * 256 + threadIdx.x;
    int m  = idx / 48;
    int c4 = idx - m * 48;
    int wbv = m >> 6, n = m & 63;
    int b  = wbv >> 8;
    int wh = (wbv >> 4) & 15;
    int ww = wbv & 15;
    int gh = (wh * 8 + (n >> 3) + 4) & 127;
    int gw = (ww * 8 + (n & 7) + 4) & 127;
    float4 v = *(const float4*)(x + ((size_t)((b * 128 + gh) * 128 + gw)) * CD
                                + c4 * 4);
    __nv_bfloat162 h01 = __float22bfloat162_rn(make_float2(v.x, v.y));
    __nv_bfloat162 h23 = __float22bfloat162_rn(make_float2(v.z, v.w));
    float2 f01 = __bfloat1622float2(h01);
    float2 f23 = __bfloat1622float2(h23);
    __nv_bfloat162 l01 = __float22bfloat162_rn(make_float2(v.x - f01.x, v.y - f01.y));
    __nv_bfloat162 l23 = __float22bfloat162_rn(make_float2(v.z - f23.x, v.w - f23.y));
    uint2 hh, ll;
    hh.x = *(uint32_t*)&h01; hh.y = *(uint32_t*)&h23;
    ll.x = *(uint32_t*)&l01; ll.y = *(uint32_t*)&l23;
    *(uint2*)(g_xh + (size_t)m * CD + c4 * 4) = hh;
    *(uint2*)(g_xl + (size_t)m * CD + c4 * 4) = ll;
}

// ---------------------------------------------------------------------------
// mma.sync GEMM with cp.async double buffering.
// MODE 0: q,k single-pass bf16 (compact smem, MINB=3).
// MODE 1: v, bf16x3; epilogue fuses LePE and emits v'^T bf16 hi/lo.
// MODE 2: proj, bf16x3, scatter to output.
// ---------------------------------------------------------------------------
template<int MODE, int MINB>
__global__ __launch_bounds__(256, MINB) void mma_gemm(
    const float* __restrict__ bias,
    float* __restrict__ outp,
    const float* __restrict__ lepe_w,
    const float* __restrict__ lepe_b)
{
    extern __shared__ char sm[];
    const uint32_t smb = smem_u32(sm);
    float* stage = (float*)sm;

    constexpr bool X3    = (MODE != 0);
    constexpr int  BNOFF = (MODE == 1) ? 6 : 0;
    constexpr uint32_t ABS   = X3 ? 32768u : 16384u;   // A double-buffer stride
    constexpr uint32_t BBASE = X3 ? 65536u : 32768u;
    constexpr uint32_t BBS   = X3 ? 16384u : 8192u;

    const __nv_bfloat16* ah = (MODE == 2) ? g_avh : g_xh;
    const __nv_bfloat16* al = (MODE == 2) ? g_avl : g_xl;
    const __nv_bfloat16* bhp = (MODE == 2) ? g_pt_hi : g_wt_hi;
    const __nv_bfloat16* blp = (MODE == 2) ? g_pt_lo : g_wt_lo;

    const int t    = threadIdx.x;
    const int w    = t >> 5;
    const int lane = t & 31;
    const int bm   = blockIdx.x;
    const int bn   = blockIdx.y;
    const int wm   = w >> 1;
    const int wn   = w & 1;
    const int g    = lane >> 2;
    const int tg   = lane & 3;

    // MODE1: stage LePE params in smem tail
    float* swb_s = (float*)(sm + 98304);
    float* slb_s = swb_s + 576;
    if (MODE == 1) {
        for (int idx = t; idx < 576; idx += 256)
            swb_s[idx] = lepe_w[(idx >> 6) * CD + bn * 64 + (idx & 63)];
        if (t < 64) slb_s[t] = lepe_b[bn * 64 + t];
    }

    auto prefetch = [&](int c, int buf) {
        const uint32_t aB = smb + buf * ABS;
        const uint32_t bB = smb + BBASE + buf * BBS;
        #pragma unroll
        for (int q = 0; q < 4; q++) {
            int idx = t + 256 * q;
            int row = idx >> 3, slot = idx & 7;
            uint32_t dst = aB + (uint32_t)(row * 128 + ((slot ^ (row & 7)) << 4));
            size_t src = (size_t)(bm * 128 + row) * CD + c * 64 + slot * 8;
            cp_async16(dst, ah + src);
            if (X3) cp_async16(dst + 16384u, al + src);
        }
        #pragma unroll
        for (int q = 0; q < 2; q++) {
            int idx = t + 256 * q;
            int row = idx >> 3, slot = idx & 7;
            uint32_t dst = bB + (uint32_t)(row * 128 + ((slot ^ (row & 7)) << 4));
            size_t src = (size_t)((BNOFF + bn) * 64 + row) * CD + c * 64 + slot * 8;
            cp_async16(dst, bhp + src);
            if (X3) cp_async16(dst + 8192u, blp + src);
        }
    };

    float acc[2][4][4] = {};

    prefetch(0, 0); CP_COMMIT();
    prefetch(1, 1); CP_COMMIT();

    #pragma unroll
    for (int c = 0; c < 3; c++) {
        if (c < 2) CP_WAIT(1); else CP_WAIT(0);
        __syncthreads();

        const char* Ah_s = sm + (c & 1) * ABS;
        const char* Al_s = Ah_s + 16384;
        const char* Bh_s = sm + BBASE + (c & 1) * BBS;
        const char* Bl_s = Bh_s + 8192;

        #pragma unroll
        for (int ks = 0; ks < 4; ks++) {
            const uint32_t s0 = (uint32_t)((2 * ks) ^ g) << 4;
            const uint32_t s1 = (uint32_t)((2 * ks + 1) ^ g) << 4;
            const uint32_t tw = (uint32_t)(tg * 4);

            uint32_t Ahf[2][4], Alf[2][4];
            #pragma unroll
            for (int i = 0; i < 2; i++) {
                const uint32_t rb = (uint32_t)((wm * 32 + i * 16 + g) * 128);
                Ahf[i][0] = *(const uint32_t*)(Ah_s + rb + s0 + tw);
                Ahf[i][1] = *(const uint32_t*)(Ah_s + rb + 1024 + s0 + tw);
                Ahf[i][2] = *(const uint32_t*)(Ah_s + rb + s1 + tw);
                Ahf[i][3] = *(const uint32_t*)(Ah_s + rb + 1024 + s1 + tw);
                if (X3) {
                    Alf[i][0] = *(const uint32_t*)(Al_s + rb + s0 + tw);
                    Alf[i][1] = *(const uint32_t*)(Al_s + rb + 1024 + s0 + tw);
                    Alf[i][2] = *(const uint32_t*)(Al_s + rb + s1 + tw);
                    Alf[i][3] = *(const uint32_t*)(Al_s + rb + 1024 + s1 + tw);
                }
            }
            uint32_t Bhf[4][2], Blf[4][2];
            #pragma unroll
            for (int j = 0; j < 4; j++) {
                const uint32_t nb = (uint32_t)((wn * 32 + j * 8 + g) * 128);
                Bhf[j][0] = *(const uint32_t*)(Bh_s + nb + s0 + tw);
                Bhf[j][1] = *(const uint32_t*)(Bh_s + nb + s1 + tw);
                if (X3) {
                    Blf[j][0] = *(const uint32_t*)(Bl_s + nb + s0 + tw);
                    Blf[j][1] = *(const uint32_t*)(Bl_s + nb + s1 + tw);
                }
            }
            #pragma unroll
            for (int i = 0; i < 2; i++)
                #pragma unroll
                for (int j = 0; j < 4; j++) {
                    mma_bf16(acc[i][j], Ahf[i], Bhf[j]);
                    if (X3) {
                        mma_bf16(acc[i][j], Ahf[i], Blf[j]);
                        mma_bf16(acc[i][j], Alf[i], Bhf[j]);
                    }
                }
        }
        __syncthreads();
        if (c + 2 < 3) { prefetch(c + 2, (c + 2) & 1); CP_COMMIT(); }
    }

    // ---- stage C to smem (stride 68 floats) ----
    #pragma unroll
    for (int i = 0; i < 2; i++) {
        int row0 = wm * 32 + i * 16 + g;
        #pragma unroll
        for (int j = 0; j < 4; j++) {
            int col = wn * 32 + j * 8 + 2 * tg;
            *(float2*)&stage[row0 * 68 + col] =
                make_float2(acc[i][j][0], acc[i][j][1]);
            *(float2*)&stage[(row0 + 8) * 68 + col] =
                make_float2(acc[i][j][2], acc[i][j][3]);
        }
    }
    __syncthreads();

    if (MODE == 1) {
        // ---- fused LePE + transpose epilogue ----
        // thread: channel col (0..63), row group rg (0..3) = 4 spatial rows.
        const int col = t & 63;
        const int rg  = t >> 6;
        const int w2  = rg >> 1;           // window within M-tile
        const int i0  = (rg & 1) * 4;      // first spatial row
        const float vb = bias[(BNOFF + bn) * 64 + col];
        const float lb = slb_s[col];
        float wgt[9];
        #pragma unroll
        for (int k9 = 0; k9 < 9; k9++) wgt[k9] = swb_s[k9 * 64 + col];
        const float* srow = stage + (w2 * 64) * 68 + col;
        float prv[8], cur[8], nxt[8];
        #pragma unroll
        for (int j = 0; j < 8; j++) {
            prv[j] = (i0 == 0) ? 0.f : (srow[((i0 - 1) * 8 + j) * 68] + vb);
            cur[j] = srow[(i0 * 8 + j) * 68] + vb;
        }
        const size_t obase =
            ((size_t)(bm * 2 + w2) * CD + bn * 64 + col) * 64;
        #pragma unroll
        for (int ir = 0; ir < 4; ir++) {
            const int i = i0 + ir;
            #pragma unroll
            for (int j = 0; j < 8; j++)
                nxt[j] = (i == 7) ? 0.f : (srow[((i + 1) * 8 + j) * 68] + vb);
            uint32_t hv[4], lv[4];
            #pragma unroll
            for (int jp = 0; jp < 4; jp++) {
                float vp2[2];
                #pragma unroll
                for (int u = 0; u < 2; u++) {
                    const int j = jp * 2 + u;
                    float a = lb;
                    a = fmaf(prv[j], wgt[1], a);
                    a = fmaf(cur[j], wgt[4], a);
                    a = fmaf(nxt[j], wgt[7], a);
                    if (j > 0) {
                        a = fmaf(prv[j - 1], wgt[0], a);
                        a = fmaf(cur[j - 1], wgt[3], a);
                        a = fmaf(nxt[j - 1], wgt[6], a);
                    }
                    if (j < 7) {
                        a = fmaf(prv[j + 1], wgt[2], a);
                        a = fmaf(cur[j + 1], wgt[5], a);
                        a = fmaf(nxt[j + 1], wgt[8], a);
                    }
                    vp2[u] = cur[j] + a;
                }
                hv[jp] = bf2_of(vp2[0], vp2[1]);
                lv[jp] = bf2_lo_of(vp2[0], vp2[1], hv[jp]);
            }
            *(uint4*)(g_vth + obase + i * 8) =
                make_uint4(hv[0], hv[1], hv[2], hv[3]);
            *(uint4*)(g_vtl + obase + i * 8) =
                make_uint4(lv[0], lv[1], lv[2], lv[3]);
            #pragma unroll
            for (int j = 0; j < 8; j++) { prv[j] = cur[j]; cur[j] = nxt[j]; }
        }
    } else {
        // ---- coalesced store with bias (MODE 0 / MODE 2) ----
        const int s = t & 15;
        float4 b4 = *(const float4*)(bias + (BNOFF + bn) * 64 + s * 4);
        #pragma unroll
        for (int it = 0; it < 8; it++) {
            int row = (t >> 4) + 16 * it;
            float4 v = *(float4*)&stage[row * 68 + s * 4];
            v.x += b4.x; v.y += b4.y; v.z += b4.z; v.w += b4.w;
            int m = bm * 128 + row;
            if (MODE == 0) {
                int colg = bn * 64 + s * 4;
                if (colg < CD) {
                    uint2 o;
                    o.x = bf2_of(v.x * ATTN_SCALE, v.y * ATTN_SCALE);
                    o.y = bf2_of(v.z * ATTN_SCALE, v.w * ATTN_SCALE);
                    *(uint2*)(g_qbf + (size_t)m * CD + colg) = o;
                } else {
                    uint2 o;
                    o.x = bf2_of(v.x, v.y);
                    o.y = bf2_of(v.z, v.w);
                    *(uint2*)(g_kbf + (size_t)m * CD + (colg - CD)) = o;
                }
            } else {
                int wbv = m >> 6, n = m & 63;
                int b  = wbv >> 8;
                int wh = (wbv >> 4) & 15;
                int ww = wbv & 15;
                int gh = (wh * 8 + (n >> 3) + 4) & 127;
                int gw = (ww * 8 + (n & 7) + 4) & 127;
                *(float4*)(outp + ((size_t)((b * 128 + gh) * 128 + gw)) * CD
                           + bn * 64 + s * 4) = v;
            }
        }
    }
}

// ---------------------------------------------------------------------------
// Kernel 2: tensor-core attention. Pure load-then-compute now.
// smem: sq[64][400B] | sk | svt_h[192][144B] | svt_l  = 106496 B.
// ---------------------------------------------------------------------------
#define SQ_OFF  0
#define SK_OFF  25600
#define SVT_H   51200
#define SVT_L   78848
#define ATTN_SMEM 106496

__global__ __launch_bounds__(384, 2) void attn4(
    const float* __restrict__ prev,
    float* __restrict__ out)
{
    extern __shared__ char sm[];
    const uint32_t smb = smem_u32(sm);

    const int t  = threadIdx.x;
    const int wb = blockIdx.x;

    // ---- one burst of cp.async: q, k, v'^T hi/lo ----
    const size_t wbase = (size_t)wb * (NTOK * CD);
    #pragma unroll
    for (int q = 0; q < 4; q++) {
        int idx = t + 384 * q;               // < 1536
        int row = idx / 24, slot = idx - row * 24;
        uint32_t d = (uint32_t)(row * 400 + slot * 16);
        cp_async16(smb + SQ_OFF + d, g_qbf + wbase + (size_t)idx * 8);
        cp_async16(smb + SK_OFF + d, g_kbf + wbase + (size_t)idx * 8);
        int c = idx >> 3, ch = idx & 7;
        uint32_t dv = (uint32_t)(c * 144 + ch * 16);
        cp_async16(smb + SVT_H + dv, g_vth + wbase + (size_t)idx * 8);
        cp_async16(smb + SVT_L + dv, g_vtl + wbase + (size_t)idx * 8);
    }
    CP_COMMIT();
    CP_WAIT(0);
    __syncthreads();

    const int w    = t >> 5;
    const int lane = t & 31;
    const int g    = lane >> 2;
    const int tg   = lane & 3;

    for (int tile = w; tile < 24; tile += 12) {
        const int h  = tile >> 2;
        const int mt = tile & 3;

        float acc[8][4];
        #pragma unroll
        for (int nt = 0; nt < 8; nt++)
            acc[nt][0] = acc[nt][1] = acc[nt][2] = acc[nt][3] = 0.f;
        #pragma unroll
        for (int ks = 0; ks < 2; ks++) {
            const uint32_t kb = (uint32_t)(h * 64 + ks * 32 + tg * 4);
            uint32_t A[4];
            const char* q0 = sm + SQ_OFF + (mt * 16 + g) * 400 + kb;
            A[0] = *(const uint32_t*)(q0);
            A[1] = *(const uint32_t*)(q0 + 8 * 400);
            A[2] = *(const uint32_t*)(q0 + 16);
            A[3] = *(const uint32_t*)(q0 + 8 * 400 + 16);
            #pragma unroll
            for (int nt = 0; nt < 8; nt++) {
                const char* k0 = sm + SK_OFF + (nt * 8 + g) * 400 + kb;
                uint32_t B[2] = { *(const uint32_t*)k0,
                                  *(const uint32_t*)(k0 + 16) };
                mma_bf16(acc[nt], A, B);
            }
        }

        const float* pr = prev + (((size_t)(wb * 6 + h)) * 64 + mt * 16) * 64;
        #pragma unroll
        for (int nt = 0; nt < 8; nt++) {
            float2 p0 = *(const float2*)(pr + g * 64 + nt * 8 + 2 * tg);
            float2 p1 = *(const float2*)(pr + (g + 8) * 64 + nt * 8 + 2 * tg);
            acc[nt][0] *= p0.x; acc[nt][1] *= p0.y;
            acc[nt][2] *= p1.x; acc[nt][3] *= p1.y;
        }

        float m0 = -1e30f, m1 = -1e30f;
        #pragma unroll
        for (int nt = 0; nt < 8; nt++) {
            m0 = fmaxf(m0, fmaxf(acc[nt][0], acc[nt][1]));
            m1 = fmaxf(m1, fmaxf(acc[nt][2], acc[nt][3]));
        }
        m0 = fmaxf(m0, __shfl_xor_sync(0xffffffffu, m0, 1));
        m0 = fmaxf(m0, __shfl_xor_sync(0xffffffffu, m0, 2));
        m1 = fmaxf(m1, __shfl_xor_sync(0xffffffffu, m1, 1));
        m1 = fmaxf(m1, __shfl_xor_sync(0xffffffffu, m1, 2));
        float s0 = 0.f, s1 = 0.f;
        #pragma unroll
        for (int nt = 0; nt < 8; nt++) {
            acc[nt][0] = __expf(acc[nt][0] - m0);
            acc[nt][1] = __expf(acc[nt][1] - m0);
            acc[nt][2] = __expf(acc[nt][2] - m1);
            acc[nt][3] = __expf(acc[nt][3] - m1);
            s0 += acc[nt][0] + acc[nt][1];
            s1 += acc[nt][2] + acc[nt][3];
        }
        s0 += __shfl_xor_sync(0xffffffffu, s0, 1);
        s0 += __shfl_xor_sync(0xffffffffu, s0, 2);
        s1 += __shfl_xor_sync(0xffffffffu, s1, 1);
        s1 += __shfl_xor_sync(0xffffffffu, s1, 2);
        const float i0 = 1.0f / s0, i1 = 1.0f / s1;

        float* ao = out + OUT_ELEMS + (((size_t)(wb * 6 + h)) * 64 + mt * 16) * 64;
        #pragma unroll
        for (int nt = 0; nt < 8; nt++) {
            acc[nt][0] *= i0; acc[nt][1] *= i0;
            acc[nt][2] *= i1; acc[nt][3] *= i1;
            *(float2*)(ao + g * 64 + nt * 8 + 2 * tg) =
                make_float2(acc[nt][0], acc[nt][1]);
            *(float2*)(ao + (g + 8) * 64 + nt * 8 + 2 * tg) =
                make_float2(acc[nt][2], acc[nt][3]);
        }

        float acc2[4][4];
        #pragma unroll
        for (int nt = 0; nt < 4; nt++)
            acc2[nt][0] = acc2[nt][1] = acc2[nt][2] = acc2[nt][3] = 0.f;
        #pragma unroll
        for (int ks = 0; ks < 4; ks++) {
            const int j0 = 2 * ks, j1 = 2 * ks + 1;
            uint32_t Ahf[4], Alf[4];
            Ahf[0] = bf2_of(acc[j0][0], acc[j0][1]);
            Alf[0] = bf2_lo_of(acc[j0][0], acc[j0][1], Ahf[0]);
            Ahf[1] = bf2_of(acc[j0][2], acc[j0][3]);
            Alf[1] = bf2_lo_of(acc[j0][2], acc[j0][3], Ahf[1]);
            Ahf[2] = bf2_of(acc[j1][0], acc[j1][1]);
            Alf[2] = bf2_lo_of(acc[j1][0], acc[j1][1], Ahf[2]);
            Ahf[3] = bf2_of(acc[j1][2], acc[j1][3]);
            Alf[3] = bf2_lo_of(acc[j1][2], acc[j1][3], Ahf[3]);
            const uint32_t jb = (uint32_t)(ks * 32 + tg * 4);
            #pragma unroll
            for (int nt = 0; nt < 4; nt++) {
                const char* vh = sm + SVT_H + (h * 32 + nt * 8 + g) * 144 + jb;
                const char* vl = sm + SVT_L + (h * 32 + nt * 8 + g) * 144 + jb;
                uint32_t Bh2[2] = { *(const uint32_t*)vh,
                                    *(const uint32_t*)(vh + 16) };
                uint32_t Bl2[2] = { *(const uint32_t*)vl,
                                    *(const uint32_t*)(vl + 16) };
                mma_bf16(acc2[nt], Ahf, Bh2);
                mma_bf16(acc2[nt], Ahf, Bl2);
                mma_bf16(acc2[nt], Alf, Bh2);
            }
        }

        const size_t r0 = (size_t)(wb * 64 + mt * 16 + g) * CD + h * 32;
        const size_t r1 = r0 + 8 * CD;
        #pragma unroll
        for (int nt = 0; nt < 4; nt++) {
            int col = nt * 8 + 2 * tg;
            uint32_t h0 = bf2_of(acc2[nt][0], acc2[nt][1]);
            uint32_t l0 = bf2_lo_of(acc2[nt][0], acc2[nt][1], h0);
            uint32_t h1 = bf2_of(acc2[nt][2], acc2[nt][3]);
            uint32_t l1 = bf2_lo_of(acc2[nt][2], acc2[nt][3], h1);
            *(uint32_t*)(g_avh + r0 + col) = h0;
            *(uint32_t*)(g_avl + r0 + col) = l0;
            *(uint32_t*)(g_avh + r1 + col) = h1;
            *(uint32_t*)(g_avl + r1 + col) = l1;
        }
    }
}

// ---------------------------------------------------------------------------
extern "C" void kernel_launch(void* const* d_in, const int* in_sizes, int n_in,
                              void* d_out, int out_size)
{
    const float* x      = (const float*)d_in[0];
    const float* prev   = (const float*)d_in[1];
    const float* qkv_w  = (const float*)d_in[2];
    const float* qkv_b  = (const float*)d_in[3];
    const float* proj_w = (const float*)d_in[4];
    const float* proj_b = (const float*)d_in[5];
    const float* lepe_w = (const float*)d_in[6];
    const float* lepe_b = (const float*)d_in[7];
    float* out = (float*)d_out;

    cudaFuncSetAttribute(attn4,
                         cudaFuncAttributeMaxDynamicSharedMemorySize, ATTN_SMEM);
    cudaFuncSetAttribute(mma_gemm<0, 3>,
                         cudaFuncAttributeMaxDynamicSharedMemorySize, 49152);
    cudaFuncSetAttribute(mma_gemm<1, 2>,
                         cudaFuncAttributeMaxDynamicSharedMemorySize, 100864);
    cudaFuncSetAttribute(mma_gemm<2, 2>,
                         cudaFuncAttributeMaxDynamicSharedMemorySize, 98304);

    prep_w<<<576, 256>>>(qkv_w, proj_w);
    prep_x<<<12288, 256>>>(x);
    mma_gemm<0, 3><<<dim3(512, 6), 256, 49152>>>(qkv_b, nullptr, nullptr, nullptr);
    mma_gemm<1, 2><<<dim3(512, 3), 256, 100864>>>(qkv_b, nullptr, lepe_w, lepe_b);
    attn4<<<NWIN, 384, ATTN_SMEM>>>(prev, out);
    mma_gemm<2, 2><<<dim3(512, 3), 256, 98304>>>(proj_b, out, nullptr, nullptr);
}